// round 5
// baseline (speedup 1.0000x reference)
#include <cuda_runtime.h>
#include <cuda_bf16.h>
#include <math.h>

#define TT 64
#define BB 256
#define EMBD 1024
#define ADIM 6
#define STOCHD 64
#define HIDD 512
#define FEATD 512
#define STATED 576
#define TBD (TT*BB)
#define NBLK 128
#define LOG2PI_F 1.837877066409345483560659472811f

typedef __nv_bfloat16 bf16;

// ---------------- scratch ----------------
__device__ float g_carryA[BB*STATED];   // [s(64)|h(512)]
__device__ float g_carryB[BB*STATED];
__device__ float g_zeroc[BB*STATED];    // zero, never written
__device__ float g_y1[BB*FEATD];
__device__ float g_y2[BB*FEATD];
__device__ float g_qmu[TBD*STOCHD];
__device__ float g_qstd[TBD*STOCHD];
__device__ float g_P[TBD*1536];
__device__ float g_PE[TBD*FEATD];
__device__ float g_Wg[512*3*576];
__device__ float g_E[TBD*EMBD];
__device__ float g_praw[TBD*2*STOCHD];
__device__ float g_e0[EMBD];
__device__ float g_e0l1[FEATD];
__device__ double g_acc[3];
__device__ unsigned g_bcount = 0;
__device__ unsigned g_bgen = 0;

__device__ bf16 g_states_bf[TBD*STATED];  // [h|s]
__device__ bf16 g_emb_bf[TBD*EMBD];
__device__ bf16 g_E_bf[TBD*EMBD];
__device__ bf16 g_pcat_bf[TBD*1536];
__device__ bf16 g_big1_bf[TBD*FEATD];
__device__ bf16 g_big2_bf[TBD*FEATD];
__device__ bf16 g_e0_bf[EMBD];
__device__ bf16 g_stW0b[512*1536];
__device__ bf16 g_stW1b[512*512];
__device__ bf16 g_stW2b[128*512];
__device__ bf16 g_epW0b[512*576];
__device__ bf16 g_epW1b[512*512];
__device__ bf16 g_epW2b[1024*512];
__device__ bf16 g_rpW0b[512*576];
__device__ bf16 g_rpW1b[512*512];

// ---------------- math ----------------
__device__ __forceinline__ float softplusf(float x) {
    return fmaxf(x, 0.f) + log1pf(expf(-fabsf(x)));
}
__device__ __forceinline__ float sigmoidf_(float x) { return 1.f / (1.f + expf(-x)); }
__device__ __forceinline__ float eluf(float x) { return x > 0.f ? x : expm1f(x); }
template<int ACT> __device__ __forceinline__ float actf(float v) {
    if (ACT == 1) return eluf(v);
    return v;
}

__device__ __forceinline__ void mma_bf16(float* c, const unsigned* a, const unsigned* b) {
    asm volatile(
        "mma.sync.aligned.m16n8k16.row.col.f32.bf16.bf16.f32 "
        "{%0,%1,%2,%3},{%4,%5,%6,%7},{%8,%9},{%0,%1,%2,%3};"
        : "+f"(c[0]), "+f"(c[1]), "+f"(c[2]), "+f"(c[3])
        : "r"(a[0]), "r"(a[1]), "r"(a[2]), "r"(a[3]), "r"(b[0]), "r"(b[1]));
}

// ---------------- grid barrier (all NBLK blocks resident) ----------------
__device__ __forceinline__ void gbar() {
    __syncthreads();
    if (threadIdx.x == 0) {
        __threadfence();
        unsigned gen = atomicAdd(&g_bgen, 0u);
        if (atomicAdd(&g_bcount, 1u) == NBLK - 1u) {
            g_bcount = 0u;
            __threadfence();
            atomicAdd(&g_bgen, 1u);
        } else {
            while (atomicAdd(&g_bgen, 0u) == gen) { __nanosleep(64); }
        }
        __threadfence();
    }
    __syncthreads();
}

// ---------------- bf16 tensor-core GEMM (unchanged from R4) ----------------
template<int ACT, bool ROWSHIFT, bool WF32, bool WBF>
__global__ __launch_bounds__(256, 2) void mma_gemm(
    const bf16* __restrict__ A, int ldA,
    const bf16* __restrict__ W, int ldW,
    const float* __restrict__ bias,
    float* __restrict__ Cf, bf16* __restrict__ Cb, int ldC, int K)
{
    __shared__ __align__(16) unsigned As[2][128 * 20];
    __shared__ __align__(16) unsigned Ws[2][128 * 20];
    int tid = threadIdx.x, lane = tid & 31, wid = tid >> 5;
    int g = lane >> 2, tg = lane & 3;
    int wr = wid >> 2, wc = wid & 3;
    int row0 = blockIdx.y * 128, col0 = blockIdx.x * 128;

    float acc[4][4][4];
#pragma unroll
    for (int mt = 0; mt < 4; mt++)
#pragma unroll
        for (int nt = 0; nt < 4; nt++)
#pragma unroll
            for (int q = 0; q < 4; q++) acc[mt][nt][q] = 0.f;

    const int nc = K / 32;
    uint4 pa[2], pb[2];
#pragma unroll
    for (int i = 0; i < 2; i++) {
        int u = tid + i * 256, row = u >> 2, q = u & 3;
        int grow = row0 + row;
        if (ROWSHIFT && grow >= 256) grow -= 256;
        pa[i] = *reinterpret_cast<const uint4*>(A + (size_t)grow * ldA + q * 8);
        pb[i] = *reinterpret_cast<const uint4*>(W + (size_t)(col0 + row) * ldW + q * 8);
    }
#pragma unroll
    for (int i = 0; i < 2; i++) {
        int u = tid + i * 256, row = u >> 2, q = u & 3;
        *reinterpret_cast<uint4*>(&As[0][row * 20 + q * 4]) = pa[i];
        *reinterpret_cast<uint4*>(&Ws[0][row * 20 + q * 4]) = pb[i];
    }
    __syncthreads();

    int buf = 0;
    for (int c = 0; c < nc; c++) {
        bool nxt = (c + 1 < nc);
        if (nxt) {
            int k0 = (c + 1) * 32;
#pragma unroll
            for (int i = 0; i < 2; i++) {
                int u = tid + i * 256, row = u >> 2, q = u & 3;
                int grow = row0 + row;
                if (ROWSHIFT && grow >= 256) grow -= 256;
                pa[i] = *reinterpret_cast<const uint4*>(A + (size_t)grow * ldA + k0 + q * 8);
                pb[i] = *reinterpret_cast<const uint4*>(W + (size_t)(col0 + row) * ldW + k0 + q * 8);
            }
        }
        const unsigned* as = As[buf];
        const unsigned* ws = Ws[buf];
#pragma unroll
        for (int ks = 0; ks < 2; ks++) {
            unsigned af[4][4], bfr[4][2];
#pragma unroll
            for (int mt = 0; mt < 4; mt++) {
                int r = wr * 64 + mt * 16 + g;
                af[mt][0] = as[r * 20 + ks * 8 + tg];
                af[mt][1] = as[(r + 8) * 20 + ks * 8 + tg];
                af[mt][2] = as[r * 20 + ks * 8 + tg + 4];
                af[mt][3] = as[(r + 8) * 20 + ks * 8 + tg + 4];
            }
#pragma unroll
            for (int nt = 0; nt < 4; nt++) {
                int n = wc * 32 + nt * 8 + g;
                bfr[nt][0] = ws[n * 20 + ks * 8 + tg];
                bfr[nt][1] = ws[n * 20 + ks * 8 + tg + 4];
            }
#pragma unroll
            for (int mt = 0; mt < 4; mt++)
#pragma unroll
                for (int nt = 0; nt < 4; nt++)
                    mma_bf16(acc[mt][nt], af[mt], bfr[nt]);
        }
        if (nxt) {
            int nb = buf ^ 1;
#pragma unroll
            for (int i = 0; i < 2; i++) {
                int u = tid + i * 256, row = u >> 2, q = u & 3;
                *reinterpret_cast<uint4*>(&As[nb][row * 20 + q * 4]) = pa[i];
                *reinterpret_cast<uint4*>(&Ws[nb][row * 20 + q * 4]) = pb[i];
            }
        }
        __syncthreads();
        buf ^= 1;
    }

#pragma unroll
    for (int mt = 0; mt < 4; mt++) {
        int r = row0 + wr * 64 + mt * 16 + g;
#pragma unroll
        for (int nt = 0; nt < 4; nt++) {
            int cc = col0 + wc * 32 + nt * 8 + tg * 2;
            float b0v = bias[cc], b1v = bias[cc + 1];
            float v00 = actf<ACT>(acc[mt][nt][0] + b0v);
            float v01 = actf<ACT>(acc[mt][nt][1] + b1v);
            float v10 = actf<ACT>(acc[mt][nt][2] + b0v);
            float v11 = actf<ACT>(acc[mt][nt][3] + b1v);
            if (WF32) {
                Cf[(size_t)r * ldC + cc]           = v00;
                Cf[(size_t)r * ldC + cc + 1]       = v01;
                Cf[(size_t)(r + 8) * ldC + cc]     = v10;
                Cf[(size_t)(r + 8) * ldC + cc + 1] = v11;
            }
            if (WBF) {
                Cb[(size_t)r * ldC + cc]           = __float2bfloat16(v00);
                Cb[(size_t)r * ldC + cc + 1]       = __float2bfloat16(v01);
                Cb[(size_t)(r + 8) * ldC + cc]     = __float2bfloat16(v10);
                Cb[(size_t)(r + 8) * ldC + cc + 1] = __float2bfloat16(v11);
            }
        }
    }
}

// ---------------- prep ----------------
__global__ void cvt_bf_k(const float* __restrict__ s, bf16* __restrict__ d, long n) {
    for (long i = blockIdx.x * (long)blockDim.x + threadIdx.x; i < n;
         i += (long)gridDim.x * blockDim.x)
        d[i] = __float2bfloat16(s[i]);
}

__global__ void prep_P(const float* __restrict__ action, const float* __restrict__ Wih,
                       const float* __restrict__ bih, const float* __restrict__ bhh,
                       float* __restrict__ P)
{
    int r = blockIdx.x;
    __shared__ float a[ADIM];
    if (threadIdx.x < ADIM) a[threadIdx.x] = action[(size_t)r * ADIM + threadIdx.x];
    __syncthreads();
    for (int j = threadIdx.x; j < 1536; j += 256) {
        float v = bih[j];
#pragma unroll
        for (int k = 0; k < ADIM; k++) v = fmaf(a[k], Wih[j * 70 + 64 + k], v);
        if (j < 1024) v += bhh[j];
        P[(size_t)r * 1536 + j] = v;
    }
}

__global__ void prep_Wg(const float* __restrict__ Wih, const float* __restrict__ Whh,
                        float* __restrict__ Wg)
{
    long total = 512L * 3 * 576;
    for (long idx = blockIdx.x * (long)blockDim.x + threadIdx.x; idx < total;
         idx += (long)gridDim.x * blockDim.x) {
        int col = (int)(idx / 1728);
        int rem = (int)(idx % 1728);
        int gate = rem / 576, k = rem % 576;
        int wrow = gate * 512 + col;
        Wg[idx] = (k < 64) ? Wih[(size_t)wrow * 70 + k] : Whh[(size_t)wrow * 512 + (k - 64)];
    }
}

// ---------------- stage bodies (device fns; exact f32) ----------------
__device__ void gru_body(
    const float* __restrict__ cin, const float* __restrict__ Wg,
    const float* __restrict__ P_t, const float* __restrict__ bhh,
    float* __restrict__ cout, bf16* __restrict__ stbf_t, int bx, int by)
{
    __shared__ float Xs[32][17];
    __shared__ float Wsm[32][49];
    int tid = threadIdx.x, tx = tid & 31, ty = tid >> 5;
    int r0 = by * 32, c0 = bx * 32;
    float accR[4] = {0,0,0,0}, accZ[4] = {0,0,0,0};
    float accNs[4] = {0,0,0,0}, accNh[4] = {0,0,0,0};

    for (int k0 = 0; k0 < STATED; k0 += 16) {
#pragma unroll
        for (int i = 0; i < 2; i++) {
            int e = tid + i * 256, row = e >> 4, kk = e & 15;
            Xs[row][kk] = cin[(size_t)(r0 + row) * STATED + k0 + kk];
        }
#pragma unroll
        for (int i = 0; i < 6; i++) {
            int e = tid + i * 256, col = e / 48, j = e % 48;
            Wsm[col][j] = Wg[(size_t)(c0 + col) * 1728 + (j >> 4) * 576 + k0 + (j & 15)];
        }
        __syncthreads();
        if (k0 < 64) {
#pragma unroll
            for (int kk = 0; kk < 16; kk++) {
                float wr = Wsm[tx][kk], wz = Wsm[tx][16 + kk], wn = Wsm[tx][32 + kk];
#pragma unroll
                for (int i = 0; i < 4; i++) {
                    float a = Xs[ty + 8 * i][kk];
                    accR[i]  = fmaf(a, wr, accR[i]);
                    accZ[i]  = fmaf(a, wz, accZ[i]);
                    accNs[i] = fmaf(a, wn, accNs[i]);
                }
            }
        } else {
#pragma unroll
            for (int kk = 0; kk < 16; kk++) {
                float wr = Wsm[tx][kk], wz = Wsm[tx][16 + kk], wn = Wsm[tx][32 + kk];
#pragma unroll
                for (int i = 0; i < 4; i++) {
                    float a = Xs[ty + 8 * i][kk];
                    accR[i]  = fmaf(a, wr, accR[i]);
                    accZ[i]  = fmaf(a, wz, accZ[i]);
                    accNh[i] = fmaf(a, wn, accNh[i]);
                }
            }
        }
        __syncthreads();
    }
#pragma unroll
    for (int i = 0; i < 4; i++) {
        int gr = r0 + ty + 8 * i, gc = c0 + tx;
        float r = sigmoidf_(accR[i] + P_t[(size_t)gr * 1536 + gc]);
        float z = sigmoidf_(accZ[i] + P_t[(size_t)gr * 1536 + 512 + gc]);
        float hn = accNh[i] + bhh[1024 + gc];
        float n = tanhf(accNs[i] + P_t[(size_t)gr * 1536 + 1024 + gc] + r * hn);
        float hp = cin[(size_t)gr * STATED + 64 + gc];
        float h = (1.f - z) * n + z * hp;
        cout[(size_t)gr * STATED + 64 + gc] = h;
        stbf_t[(size_t)gr * STATED + gc] = __float2bfloat16(h);
    }
}

__device__ void lin_body(
    const float* __restrict__ X, int ldX,
    const float* __restrict__ W, int ldW,
    const float* __restrict__ Add, int ldAdd,
    float* __restrict__ Y, int ldY, int K, int bx, int by)
{
    __shared__ float Xs[32][17];
    __shared__ float Wsm[32][17];
    int tid = threadIdx.x, tx = tid & 31, ty = tid >> 5;
    int r0 = by * 32, c0 = bx * 32;
    float acc[4] = {0,0,0,0};
    for (int k0 = 0; k0 < K; k0 += 16) {
#pragma unroll
        for (int i = 0; i < 2; i++) {
            int e = tid + i * 256, row = e >> 4, kk = e & 15;
            Xs[row][kk]  = X[(size_t)(r0 + row) * ldX + k0 + kk];
            Wsm[row][kk] = W[(size_t)(c0 + row) * ldW + k0 + kk];
        }
        __syncthreads();
#pragma unroll
        for (int kk = 0; kk < 16; kk++) {
            float w = Wsm[tx][kk];
#pragma unroll
            for (int i = 0; i < 4; i++)
                acc[i] = fmaf(Xs[ty + 8 * i][kk], w, acc[i]);
        }
        __syncthreads();
    }
#pragma unroll
    for (int i = 0; i < 4; i++) {
        int gr = r0 + ty + 8 * i, gc = c0 + tx;
        Y[(size_t)gr * ldY + gc] = eluf(acc[i] + Add[(size_t)gr * ldAdd + gc]);
    }
}

__device__ void l2s_body(
    const float* __restrict__ y2, const float* __restrict__ W2, const float* __restrict__ b2,
    const float* __restrict__ eps_t, float* __restrict__ qmu_t, float* __restrict__ qstd_t,
    float* __restrict__ cout, bf16* __restrict__ stbf_t, int bx, int by)
{
    __shared__ float Xs[16][17];
    __shared__ float Wm[32][17];
    __shared__ float Wsd[32][17];
    int tid = threadIdx.x, tx = tid & 31, ty = tid >> 5;
    int r0 = by * 16, c0 = bx * 32;
    float accM[2] = {0,0}, accS[2] = {0,0};
    for (int k0 = 0; k0 < 512; k0 += 16) {
        { int row = tid >> 4, kk = tid & 15;
          Xs[row][kk] = y2[(size_t)(r0 + row) * 512 + k0 + kk]; }
#pragma unroll
        for (int i = 0; i < 2; i++) {
            int e = tid + i * 256, col = e >> 4, kk = e & 15;
            Wm[col][kk]  = W2[(size_t)(c0 + col) * 512 + k0 + kk];
            Wsd[col][kk] = W2[(size_t)(64 + c0 + col) * 512 + k0 + kk];
        }
        __syncthreads();
#pragma unroll
        for (int kk = 0; kk < 16; kk++) {
            float wm = Wm[tx][kk], ws = Wsd[tx][kk];
#pragma unroll
            for (int i = 0; i < 2; i++) {
                float a = Xs[ty + 8 * i][kk];
                accM[i] = fmaf(a, wm, accM[i]);
                accS[i] = fmaf(a, ws, accS[i]);
            }
        }
        __syncthreads();
    }
#pragma unroll
    for (int i = 0; i < 2; i++) {
        int gr = r0 + ty + 8 * i, gc = c0 + tx;
        float mu = accM[i] + b2[gc];
        float sd = softplusf(accS[i] + b2[64 + gc]) + 1e-4f;
        float s = fmaf(sd, eps_t[(size_t)gr * 64 + gc], mu);
        qmu_t[(size_t)gr * 64 + gc] = mu;
        qstd_t[(size_t)gr * 64 + gc] = sd;
        cout[(size_t)gr * STATED + gc] = s;
        stbf_t[(size_t)gr * STATED + 512 + gc] = __float2bfloat16(s);
    }
}

// ---------------- persistent recurrence kernel ----------------
__global__ __launch_bounds__(256) void recur_k(
    const float* __restrict__ Wg, const float* __restrict__ P,
    const float* __restrict__ bhh, const float* __restrict__ st_W0,
    const float* __restrict__ st_W1, const float* __restrict__ st_b1,
    const float* __restrict__ st_W2, const float* __restrict__ st_b2,
    const float* __restrict__ PE, const float* __restrict__ eps,
    float* __restrict__ qmu, float* __restrict__ qstd, bf16* __restrict__ stbf,
    float* __restrict__ carryA, float* __restrict__ carryB,
    const float* __restrict__ zeroc, float* __restrict__ y1, float* __restrict__ y2)
{
    int b = blockIdx.x;
    int bx16 = b & 15, by8 = b >> 4;      // (16,8) mapping

    for (int t = 0; t < TT; t++) {
        const float* cin = (t == 0) ? zeroc : ((t & 1) ? carryB : carryA);
        float* cout = ((t + 1) & 1) ? carryB : carryA;
        bf16* st_t = stbf + (size_t)t * BB * STATED;

        gru_body(cin, Wg, P + (size_t)t * BB * 1536, bhh, cout, st_t, bx16, by8);
        gbar();
        lin_body(cout + 64, STATED, st_W0, 1536,
                 PE + (size_t)t * BB * FEATD, FEATD, y1, FEATD, HIDD, bx16, by8);
        gbar();
        lin_body(y1, FEATD, st_W1, FEATD, st_b1, 0, y2, FEATD, FEATD, bx16, by8);
        gbar();
        if (b < 32)
            l2s_body(y2, st_W2, st_b2, eps + (size_t)t * BB * STOCHD,
                     qmu + (size_t)t * BB * STOCHD, qstd + (size_t)t * BB * STOCHD,
                     cout, st_t, b & 1, b >> 1);
        gbar();
    }
}

// ---------------- misc ----------------
__global__ void e0_l1(const float* __restrict__ ep_b0, const float* __restrict__ ep_W1,
                      const float* __restrict__ ep_b1, float* __restrict__ l1)
{
    __shared__ float x0[512];
    for (int k = threadIdx.x; k < 512; k += 256) x0[k] = eluf(ep_b0[k]);
    __syncthreads();
    for (int o = threadIdx.x; o < 512; o += 256) {
        float v = ep_b1[o];
        for (int k = 0; k < 512; k++) v = fmaf(x0[k], ep_W1[(size_t)o * 512 + k], v);
        l1[o] = eluf(v);
    }
}

__global__ void e0_head(const float* __restrict__ l1, const float* __restrict__ ep_W2,
                        const float* __restrict__ ep_b2, float* __restrict__ e0)
{
    int o = blockIdx.x * 256 + threadIdx.x;
    float v = ep_b2[o];
    for (int k = 0; k < 512; k++) v = fmaf(l1[k], ep_W2[(size_t)o * 512 + k], v);
    e0[o] = v;
}

__global__ void build_pcat(const bf16* __restrict__ stbf, const bf16* __restrict__ Ebf,
                           const bf16* __restrict__ e0bf, bf16* __restrict__ out)
{
    int r = blockIdx.x;
    const bf16* src = (r < 256) ? e0bf : (Ebf + (size_t)(r - 256) * EMBD);
    bf16* o = out + (size_t)r * 1536;
    const bf16* st = stbf + (size_t)r * STATED;
    for (int c = threadIdx.x; c < 1536; c += 256)
        o[c] = (c < 512) ? st[c] : src[c - 512];
}

// ---------------- reductions ----------------
__global__ void zero_acc_k(double* acc) { if (threadIdx.x < 3) acc[threadIdx.x] = 0.0; }

__global__ void kl_reduce_k(const float* __restrict__ praw, const float* __restrict__ qmu,
                            const float* __restrict__ qstd, double* __restrict__ acc)
{
    __shared__ double sh[256];
    double s = 0.0;
    long total = (long)TBD * STOCHD;
    for (long idx = blockIdx.x * (long)blockDim.x + threadIdx.x; idx < total;
         idx += (long)gridDim.x * blockDim.x) {
        int r = (int)(idx >> 6), i = (int)(idx & 63);
        float pmu = praw[(size_t)r * 128 + i];
        float psd = softplusf(praw[(size_t)r * 128 + 64 + i]) + 1e-4f;
        float qm = qmu[idx], qs = qstd[idx];
        float d = qm - pmu;
        s += (double)(logf(psd / qs) + (qs * qs + d * d) / (2.f * psd * psd) - 0.5f);
    }
    sh[threadIdx.x] = s; __syncthreads();
    for (int o = 128; o > 0; o >>= 1) {
        if (threadIdx.x < o) sh[threadIdx.x] += sh[threadIdx.x + o];
        __syncthreads();
    }
    if (threadIdx.x == 0) atomicAdd(acc, sh[0]);
}

__global__ void emb_reduce_k(const float* __restrict__ emb, const float* __restrict__ embmu,
                             double* __restrict__ acc)
{
    __shared__ double sh[256];
    double s = 0.0;
    long total = (long)TBD * EMBD;
    for (long idx = blockIdx.x * (long)blockDim.x + threadIdx.x; idx < total;
         idx += (long)gridDim.x * blockDim.x) {
        float d = emb[idx] - embmu[idx];
        s += (double)(0.5f * d * d + 0.5f * LOG2PI_F);
    }
    sh[threadIdx.x] = s; __syncthreads();
    for (int o = 128; o > 0; o >>= 1) {
        if (threadIdx.x < o) sh[threadIdx.x] += sh[threadIdx.x + o];
        __syncthreads();
    }
    if (threadIdx.x == 0) atomicAdd(acc, sh[0]);
}

__global__ void reward_reduce_k(const bf16* __restrict__ big2, const float* __restrict__ W,
                                const float* __restrict__ bias, const float* __restrict__ reward,
                                double* __restrict__ acc)
{
    __shared__ double sh[8];
    int lane = threadIdx.x & 31, wib = threadIdx.x >> 5;
    int gwarp = (blockIdx.x * blockDim.x + threadIdx.x) >> 5;
    int nwarps = (gridDim.x * blockDim.x) >> 5;
    double local = 0.0;
    for (int r = gwarp; r < TBD; r += nwarps) {
        float sum = 0.f;
        const bf16* row = big2 + (size_t)r * FEATD;
        for (int k = lane; k < FEATD; k += 32)
            sum = fmaf(__bfloat162float(row[k]), W[k], sum);
#pragma unroll
        for (int o = 16; o > 0; o >>= 1) sum += __shfl_xor_sync(0xffffffffu, sum, o);
        if (lane == 0) {
            float d = reward[r] - (sum + bias[0]);
            local += (double)(0.5f * d * d + 0.5f * LOG2PI_F);
        }
    }
    if (lane == 0) sh[wib] = local;
    __syncthreads();
    if (threadIdx.x == 0) {
        double t = 0.0;
        for (int i = 0; i < 8; i++) t += sh[i];
        atomicAdd(acc, t);
    }
}

__global__ void finalize_k(const double* __restrict__ acc, float* __restrict__ out, int n) {
    double inv = 1.0 / (double)(TT * BB);
    float loss = (float)((acc[0] + acc[1] + acc[2]) * inv);
    for (int i = 0; i < n; i++) out[i] = loss;
}

// ---------------- host ----------------
static void* symaddr(const void* sym) {
    void* p = nullptr;
    cudaGetSymbolAddress(&p, sym);
    return p;
}

extern "C" void kernel_launch(void* const* d_in, const int* in_sizes, int n_in,
                              void* d_out, int out_size)
{
    const float* emb     = (const float*)d_in[0];
    const float* action  = (const float*)d_in[1];
    const float* reward  = (const float*)d_in[2];
    const float* eps     = (const float*)d_in[3];
    const float* gru_Wih = (const float*)d_in[4];
    const float* gru_bih = (const float*)d_in[5];
    const float* gru_Whh = (const float*)d_in[6];
    const float* gru_bhh = (const float*)d_in[7];
    const float* st_W0 = (const float*)d_in[8];  const float* st_b0 = (const float*)d_in[9];
    const float* st_W1 = (const float*)d_in[10]; const float* st_b1 = (const float*)d_in[11];
    const float* st_W2 = (const float*)d_in[12]; const float* st_b2 = (const float*)d_in[13];
    const float* ep_W0 = (const float*)d_in[14]; const float* ep_b0 = (const float*)d_in[15];
    const float* ep_W1 = (const float*)d_in[16]; const float* ep_b1 = (const float*)d_in[17];
    const float* ep_W2 = (const float*)d_in[18]; const float* ep_b2 = (const float*)d_in[19];
    const float* rp_W0 = (const float*)d_in[20]; const float* rp_b0 = (const float*)d_in[21];
    const float* rp_W1 = (const float*)d_in[22]; const float* rp_b1 = (const float*)d_in[23];
    const float* rp_W2 = (const float*)d_in[24]; const float* rp_b2 = (const float*)d_in[25];

    float* carryA = (float*)symaddr(g_carryA);
    float* carryB = (float*)symaddr(g_carryB);
    float* zeroc  = (float*)symaddr(g_zeroc);
    float* y1     = (float*)symaddr(g_y1);
    float* y2     = (float*)symaddr(g_y2);
    float* qmu    = (float*)symaddr(g_qmu);
    float* qstd   = (float*)symaddr(g_qstd);
    float* P      = (float*)symaddr(g_P);
    float* PE     = (float*)symaddr(g_PE);
    float* Wg     = (float*)symaddr(g_Wg);
    float* E      = (float*)symaddr(g_E);
    float* praw   = (float*)symaddr(g_praw);
    float* e0     = (float*)symaddr(g_e0);
    float* e0l1   = (float*)symaddr(g_e0l1);
    double* acc   = (double*)symaddr(g_acc);
    bf16* stbf   = (bf16*)symaddr(g_states_bf);
    bf16* embbf  = (bf16*)symaddr(g_emb_bf);
    bf16* Ebf    = (bf16*)symaddr(g_E_bf);
    bf16* pcatbf = (bf16*)symaddr(g_pcat_bf);
    bf16* big1bf = (bf16*)symaddr(g_big1_bf);
    bf16* big2bf = (bf16*)symaddr(g_big2_bf);
    bf16* e0bf   = (bf16*)symaddr(g_e0_bf);
    bf16* stW0b  = (bf16*)symaddr(g_stW0b);
    bf16* stW1b  = (bf16*)symaddr(g_stW1b);
    bf16* stW2b  = (bf16*)symaddr(g_stW2b);
    bf16* epW0b  = (bf16*)symaddr(g_epW0b);
    bf16* epW1b  = (bf16*)symaddr(g_epW1b);
    bf16* epW2b  = (bf16*)symaddr(g_epW2b);
    bf16* rpW0b  = (bf16*)symaddr(g_rpW0b);
    bf16* rpW1b  = (bf16*)symaddr(g_rpW1b);

    zero_acc_k<<<1, 32>>>(acc);

    // conversions + prep
    cvt_bf_k<<<2048, 256>>>(emb,   embbf, (long)TBD * EMBD);
    cvt_bf_k<<<512, 256>>>(st_W0, stW0b, 512L * 1536);
    cvt_bf_k<<<256, 256>>>(st_W1, stW1b, 512L * 512);
    cvt_bf_k<<<64,  256>>>(st_W2, stW2b, 128L * 512);
    cvt_bf_k<<<256, 256>>>(ep_W0, epW0b, 512L * 576);
    cvt_bf_k<<<256, 256>>>(ep_W1, epW1b, 512L * 512);
    cvt_bf_k<<<512, 256>>>(ep_W2, epW2b, 1024L * 512);
    cvt_bf_k<<<256, 256>>>(rp_W0, rpW0b, 512L * 576);
    cvt_bf_k<<<256, 256>>>(rp_W1, rpW1b, 512L * 512);
    prep_P<<<TBD, 256>>>(action, gru_Wih, gru_bih, gru_bhh, P);
    prep_Wg<<<1024, 256>>>(gru_Wih, gru_Whh, Wg);
    e0_l1<<<1, 256>>>(ep_b0, ep_W1, ep_b1, e0l1);
    e0_head<<<4, 256>>>(e0l1, ep_W2, ep_b2, e0);
    cvt_bf_k<<<4, 256>>>(e0, e0bf, EMBD);

    // PE = emb_prev @ st_W0[:,512:1536]^T + st_b0   (tensor core, rowShift)
    mma_gemm<0, true, true, false><<<dim3(4, 128), 256>>>(
        embbf, EMBD, stW0b + 512, 1536, st_b0, PE, nullptr, FEATD, EMBD);

    // sequential recurrence: ONE persistent kernel, 128 resident blocks
    recur_k<<<NBLK, 256>>>(Wg, P, gru_bhh, st_W0, st_W1, st_b1, st_W2, st_b2,
                           PE, eps, qmu, qstd, stbf, carryA, carryB, zeroc, y1, y2);

    // shared ep-MLP: E = ep_mlp(states) = emb_mu; row-shifted = pre_emb
    mma_gemm<1, false, false, true><<<dim3(4, 128), 256>>>(
        stbf, STATED, epW0b, STATED, ep_b0, nullptr, big1bf, FEATD, STATED);
    mma_gemm<1, false, false, true><<<dim3(4, 128), 256>>>(
        big1bf, FEATD, epW1b, FEATD, ep_b1, nullptr, big2bf, FEATD, FEATD);
    mma_gemm<0, false, true, true><<<dim3(8, 128), 256>>>(
        big2bf, FEATD, epW2b, FEATD, ep_b2, E, Ebf, EMBD, FEATD);

    // prior path
    build_pcat<<<TBD, 256>>>(stbf, Ebf, e0bf, pcatbf);
    mma_gemm<1, false, false, true><<<dim3(4, 128), 256>>>(
        pcatbf, 1536, stW0b, 1536, st_b0, nullptr, big1bf, FEATD, 1536);
    mma_gemm<1, false, false, true><<<dim3(4, 128), 256>>>(
        big1bf, FEATD, stW1b, FEATD, st_b1, nullptr, big2bf, FEATD, FEATD);
    mma_gemm<0, false, true, false><<<dim3(1, 128), 256>>>(
        big2bf, FEATD, stW2b, FEATD, st_b2, praw, nullptr, 128, FEATD);
    kl_reduce_k<<<1024, 256>>>(praw, qmu, qstd, acc + 0);

    // emb loss
    emb_reduce_k<<<2048, 256>>>(emb, E, acc + 1);

    // reward loss
    mma_gemm<1, false, false, true><<<dim3(4, 128), 256>>>(
        stbf, STATED, rpW0b, STATED, rp_b0, nullptr, big1bf, FEATD, STATED);
    mma_gemm<1, false, false, true><<<dim3(4, 128), 256>>>(
        big1bf, FEATD, rpW1b, FEATD, rp_b1, nullptr, big2bf, FEATD, FEATD);
    reward_reduce_k<<<512, 256>>>(big2bf, rp_W2, rp_b2, reward, acc + 2);

    finalize_k<<<1, 1>>>(acc, (float*)d_out, out_size);
}

// round 6
// speedup vs baseline: 1.8439x; 1.8439x over previous
#include <cuda_runtime.h>
#include <cuda_bf16.h>
#include <math.h>

#define TT 64
#define BB 256
#define EMBD 1024
#define ADIM 6
#define STOCHD 64
#define HIDD 512
#define FEATD 512
#define STATED 576
#define TBD (TT*BB)
#define NBLK 128
#define LOG2PI_F 1.837877066409345483560659472811f

typedef __nv_bfloat16 bf16;

// ---------------- scratch ----------------
__device__ float g_carryA[BB*STATED];   // [s(64)|h(512)]
__device__ float g_carryB[BB*STATED];
__device__ float g_zeroc[BB*STATED];
__device__ float g_y1[BB*FEATD];
__device__ float g_y2[BB*FEATD];
__device__ float g_qmu[TBD*STOCHD];
__device__ float g_qstd[TBD*STOCHD];
__device__ float g_P[TBD*1536];
__device__ float g_PE[TBD*FEATD];
__device__ float g_E[TBD*EMBD];
__device__ float g_praw[TBD*2*STOCHD];
__device__ float g_e0[EMBD];
__device__ float g_e0l1[FEATD];
__device__ float g_b2p[128];
__device__ double g_acc[3];
__device__ unsigned g_bcount = 0;
__device__ unsigned g_bgen = 0;

__device__ bf16 g_states_bf[TBD*STATED];
__device__ bf16 g_emb_bf[TBD*EMBD];
__device__ bf16 g_E_bf[TBD*EMBD];
__device__ bf16 g_pcat_bf[TBD*1536];
__device__ bf16 g_big1_bf[TBD*FEATD];
__device__ bf16 g_big2_bf[TBD*FEATD];
__device__ bf16 g_e0_bf[EMBD];
__device__ bf16 g_stW0b[512*1536];
__device__ bf16 g_stW1b[512*512];
__device__ bf16 g_stW2b[128*512];
__device__ bf16 g_epW0b[512*576];
__device__ bf16 g_epW1b[512*512];
__device__ bf16 g_epW2b[1024*512];
__device__ bf16 g_rpW0b[512*576];
__device__ bf16 g_rpW1b[512*512];
// split hi/lo weights for the sequential path
__device__ bf16 g_WGh[2048*576];
__device__ bf16 g_WGl[2048*576];
__device__ bf16 g_W0hh[512*512];
__device__ bf16 g_W0hl[512*512];
__device__ bf16 g_W1h[512*512];
__device__ bf16 g_W1l[512*512];
__device__ bf16 g_W2h[128*512];
__device__ bf16 g_W2l[128*512];

// ---------------- math ----------------
__device__ __forceinline__ float softplusf(float x) {
    return fmaxf(x, 0.f) + log1pf(expf(-fabsf(x)));
}
__device__ __forceinline__ float sigmoidf_(float x) { return 1.f / (1.f + expf(-x)); }
__device__ __forceinline__ float eluf(float x) { return x > 0.f ? x : expm1f(x); }
template<int ACT> __device__ __forceinline__ float actf(float v) {
    if (ACT == 1) return eluf(v);
    return v;
}

__device__ __forceinline__ void mma_bf16(float* c, const unsigned* a, const unsigned* b) {
    asm volatile(
        "mma.sync.aligned.m16n8k16.row.col.f32.bf16.bf16.f32 "
        "{%0,%1,%2,%3},{%4,%5,%6,%7},{%8,%9},{%0,%1,%2,%3};"
        : "+f"(c[0]), "+f"(c[1]), "+f"(c[2]), "+f"(c[3])
        : "r"(a[0]), "r"(a[1]), "r"(a[2]), "r"(a[3]), "r"(b[0]), "r"(b[1]));
}

// split two f32 into packed bf16 hi-word and lo-word (k-consecutive pair)
__device__ __forceinline__ void split2(float x, float y, unsigned& h, unsigned& l) {
    bf16 hx = __float2bfloat16(x), hy = __float2bfloat16(y);
    bf16 lx = __float2bfloat16(x - __bfloat162float(hx));
    bf16 ly = __float2bfloat16(y - __bfloat162float(hy));
    h = ((unsigned)__bfloat16_as_ushort(hy) << 16) | __bfloat16_as_ushort(hx);
    l = ((unsigned)__bfloat16_as_ushort(ly) << 16) | __bfloat16_as_ushort(lx);
}

// ---------------- grid barrier ----------------
__device__ __forceinline__ void gbar() {
    __threadfence();
    __syncthreads();
    if (threadIdx.x == 0) {
        unsigned gen = atomicAdd(&g_bgen, 0u);
        if (atomicAdd(&g_bcount, 1u) == NBLK - 1u) {
            g_bcount = 0u;
            __threadfence();
            atomicAdd(&g_bgen, 1u);
        } else {
            while (atomicAdd(&g_bgen, 0u) == gen) { __nanosleep(32); }
        }
    }
    __syncthreads();
}

// ---------------- bf16 tensor-core GEMM (batched; proven in R4) ----------------
template<int ACT, bool ROWSHIFT, bool WF32, bool WBF>
__global__ __launch_bounds__(256, 2) void mma_gemm(
    const bf16* __restrict__ A, int ldA,
    const bf16* __restrict__ W, int ldW,
    const float* __restrict__ bias,
    float* __restrict__ Cf, bf16* __restrict__ Cb, int ldC, int K)
{
    __shared__ __align__(16) unsigned As[2][128 * 20];
    __shared__ __align__(16) unsigned Ws[2][128 * 20];
    int tid = threadIdx.x, lane = tid & 31, wid = tid >> 5;
    int g = lane >> 2, tg = lane & 3;
    int wr = wid >> 2, wc = wid & 3;
    int row0 = blockIdx.y * 128, col0 = blockIdx.x * 128;

    float acc[4][4][4];
#pragma unroll
    for (int mt = 0; mt < 4; mt++)
#pragma unroll
        for (int nt = 0; nt < 4; nt++)
#pragma unroll
            for (int q = 0; q < 4; q++) acc[mt][nt][q] = 0.f;

    const int nc = K / 32;
    uint4 pa[2], pb[2];
#pragma unroll
    for (int i = 0; i < 2; i++) {
        int u = tid + i * 256, row = u >> 2, q = u & 3;
        int grow = row0 + row;
        if (ROWSHIFT && grow >= 256) grow -= 256;
        pa[i] = *reinterpret_cast<const uint4*>(A + (size_t)grow * ldA + q * 8);
        pb[i] = *reinterpret_cast<const uint4*>(W + (size_t)(col0 + row) * ldW + q * 8);
    }
#pragma unroll
    for (int i = 0; i < 2; i++) {
        int u = tid + i * 256, row = u >> 2, q = u & 3;
        *reinterpret_cast<uint4*>(&As[0][row * 20 + q * 4]) = pa[i];
        *reinterpret_cast<uint4*>(&Ws[0][row * 20 + q * 4]) = pb[i];
    }
    __syncthreads();

    int buf = 0;
    for (int c = 0; c < nc; c++) {
        bool nxt = (c + 1 < nc);
        if (nxt) {
            int k0 = (c + 1) * 32;
#pragma unroll
            for (int i = 0; i < 2; i++) {
                int u = tid + i * 256, row = u >> 2, q = u & 3;
                int grow = row0 + row;
                if (ROWSHIFT && grow >= 256) grow -= 256;
                pa[i] = *reinterpret_cast<const uint4*>(A + (size_t)grow * ldA + k0 + q * 8);
                pb[i] = *reinterpret_cast<const uint4*>(W + (size_t)(col0 + row) * ldW + k0 + q * 8);
            }
        }
        const unsigned* as = As[buf];
        const unsigned* ws = Ws[buf];
#pragma unroll
        for (int ks = 0; ks < 2; ks++) {
            unsigned af[4][4], bfr[4][2];
#pragma unroll
            for (int mt = 0; mt < 4; mt++) {
                int r = wr * 64 + mt * 16 + g;
                af[mt][0] = as[r * 20 + ks * 8 + tg];
                af[mt][1] = as[(r + 8) * 20 + ks * 8 + tg];
                af[mt][2] = as[r * 20 + ks * 8 + tg + 4];
                af[mt][3] = as[(r + 8) * 20 + ks * 8 + tg + 4];
            }
#pragma unroll
            for (int nt = 0; nt < 4; nt++) {
                int n = wc * 32 + nt * 8 + g;
                bfr[nt][0] = ws[n * 20 + ks * 8 + tg];
                bfr[nt][1] = ws[n * 20 + ks * 8 + tg + 4];
            }
#pragma unroll
            for (int mt = 0; mt < 4; mt++)
#pragma unroll
                for (int nt = 0; nt < 4; nt++)
                    mma_bf16(acc[mt][nt], af[mt], bfr[nt]);
        }
        if (nxt) {
            int nb = buf ^ 1;
#pragma unroll
            for (int i = 0; i < 2; i++) {
                int u = tid + i * 256, row = u >> 2, q = u & 3;
                *reinterpret_cast<uint4*>(&As[nb][row * 20 + q * 4]) = pa[i];
                *reinterpret_cast<uint4*>(&Ws[nb][row * 20 + q * 4]) = pb[i];
            }
        }
        __syncthreads();
        buf ^= 1;
    }

#pragma unroll
    for (int mt = 0; mt < 4; mt++) {
        int r = row0 + wr * 64 + mt * 16 + g;
#pragma unroll
        for (int nt = 0; nt < 4; nt++) {
            int cc = col0 + wc * 32 + nt * 8 + tg * 2;
            float b0v = bias[cc], b1v = bias[cc + 1];
            float v00 = actf<ACT>(acc[mt][nt][0] + b0v);
            float v01 = actf<ACT>(acc[mt][nt][1] + b1v);
            float v10 = actf<ACT>(acc[mt][nt][2] + b0v);
            float v11 = actf<ACT>(acc[mt][nt][3] + b1v);
            if (WF32) {
                Cf[(size_t)r * ldC + cc]           = v00;
                Cf[(size_t)r * ldC + cc + 1]       = v01;
                Cf[(size_t)(r + 8) * ldC + cc]     = v10;
                Cf[(size_t)(r + 8) * ldC + cc + 1] = v11;
            }
            if (WBF) {
                Cb[(size_t)r * ldC + cc]           = __float2bfloat16(v00);
                Cb[(size_t)r * ldC + cc + 1]       = __float2bfloat16(v01);
                Cb[(size_t)(r + 8) * ldC + cc]     = __float2bfloat16(v10);
                Cb[(size_t)(r + 8) * ldC + cc + 1] = __float2bfloat16(v11);
            }
        }
    }
}

// ---------------- prep ----------------
__global__ void cvt_bf_k(const float* __restrict__ s, bf16* __restrict__ d, long n) {
    for (long i = blockIdx.x * (long)blockDim.x + threadIdx.x; i < n;
         i += (long)gridDim.x * blockDim.x)
        d[i] = __float2bfloat16(s[i]);
}

__global__ void prep_P(const float* __restrict__ action, const float* __restrict__ Wih,
                       const float* __restrict__ bih, const float* __restrict__ bhh,
                       float* __restrict__ P)
{
    int r = blockIdx.x;
    __shared__ float a[ADIM];
    if (threadIdx.x < ADIM) a[threadIdx.x] = action[(size_t)r * ADIM + threadIdx.x];
    __syncthreads();
    for (int j = threadIdx.x; j < 1536; j += 256) {
        float v = bih[j];
#pragma unroll
        for (int k = 0; k < ADIM; k++) v = fmaf(a[k], Wih[j * 70 + 64 + k], v);
        if (j < 1024) v += bhh[j];
        P[(size_t)r * 1536 + j] = v;
    }
}

// gate-interleaved packed GRU weights, split hi/lo.
// col c: jb=c>>7, gate=(c>>5)&3, jl=c&31, j=jb*32+jl; gates: 0=r,1=z,2=ns(s only),3=nh(h only)
__global__ void prep_WG(const float* __restrict__ Wih, const float* __restrict__ Whh,
                        bf16* __restrict__ WGh, bf16* __restrict__ WGl)
{
    long total = 2048L * 576;
    for (long idx = blockIdx.x * (long)blockDim.x + threadIdx.x; idx < total;
         idx += (long)gridDim.x * blockDim.x) {
        int c = (int)(idx / 576), k = (int)(idx % 576);
        int jb = c >> 7, gs = (c >> 5) & 3, jl = c & 31, j = jb * 32 + jl;
        float v = 0.f;
        if (gs == 0)      v = (k < 64) ? Wih[j * 70 + k] : Whh[(size_t)j * 512 + k - 64];
        else if (gs == 1) v = (k < 64) ? Wih[(512 + j) * 70 + k] : Whh[(size_t)(512 + j) * 512 + k - 64];
        else if (gs == 2) v = (k < 64) ? Wih[(1024 + j) * 70 + k] : 0.f;
        else              v = (k < 64) ? 0.f : Whh[(size_t)(1024 + j) * 512 + k - 64];
        bf16 h = __float2bfloat16(v);
        WGh[idx] = h;
        WGl[idx] = __float2bfloat16(v - __bfloat162float(h));
    }
}

__global__ void prep_split(const float* __restrict__ src, int ld, int K,
                           bf16* __restrict__ hi, bf16* __restrict__ lo, long n)
{
    for (long idx = blockIdx.x * (long)blockDim.x + threadIdx.x; idx < n;
         idx += (long)gridDim.x * blockDim.x) {
        int row = (int)(idx / K), k = (int)(idx % K);
        float v = src[(size_t)row * ld + k];
        bf16 h = __float2bfloat16(v);
        hi[idx] = h;
        lo[idx] = __float2bfloat16(v - __bfloat162float(h));
    }
}

// W2 rows interleaved (mu_i, std_i) pairs + matching bias
__global__ void prep_W2p(const float* __restrict__ W2, const float* __restrict__ b2,
                         bf16* __restrict__ hi, bf16* __restrict__ lo, float* __restrict__ b2p)
{
    long total = 128L * 512;
    for (long idx = blockIdx.x * (long)blockDim.x + threadIdx.x; idx < total;
         idx += (long)gridDim.x * blockDim.x) {
        int c = (int)(idx / 512), k = (int)(idx % 512);
        int sr = (c & 1) ? (64 + (c >> 1)) : (c >> 1);
        float v = W2[(size_t)sr * 512 + k];
        bf16 h = __float2bfloat16(v);
        hi[idx] = h;
        lo[idx] = __float2bfloat16(v - __bfloat162float(h));
        if (k == 0) b2p[c] = b2[sr];
    }
}

// ---------------- 16x64-tile split-bf16 MMA (K=512) for L0/L1/L2 ----------------
__device__ __forceinline__ void gemm16(
    const float* __restrict__ A, int ldA,
    const bf16* __restrict__ Wh, const bf16* __restrict__ Wl,
    int r0, int c0, float* acc, unsigned* SM,
    int tid, int wid, int g, int tg)
{
    unsigned* AsH = SM;        unsigned* AsL = SM + 320;
    unsigned* WsH = SM + 640;  unsigned* WsL = SM + 1920;
    acc[0] = acc[1] = acc[2] = acc[3] = 0.f;
    int ar = tid >> 3, aq = tid & 7;
    int wrow = tid >> 2, wq = tid & 3;
    bool aact = tid < 128;
    float4 fa = make_float4(0.f, 0.f, 0.f, 0.f);
    uint4 vh, vl;
    if (aact) fa = *reinterpret_cast<const float4*>(A + (size_t)(r0 + ar) * ldA + aq * 4);
    vh = *reinterpret_cast<const uint4*>(Wh + (size_t)(c0 + wrow) * 512 + wq * 8);
    vl = *reinterpret_cast<const uint4*>(Wl + (size_t)(c0 + wrow) * 512 + wq * 8);
    for (int c = 0; c < 16; c++) {
        if (aact) {
            unsigned h0, l0, h1, l1;
            split2(fa.x, fa.y, h0, l0); split2(fa.z, fa.w, h1, l1);
            AsH[ar * 20 + aq * 2] = h0; AsH[ar * 20 + aq * 2 + 1] = h1;
            AsL[ar * 20 + aq * 2] = l0; AsL[ar * 20 + aq * 2 + 1] = l1;
        }
        *reinterpret_cast<uint4*>(&WsH[wrow * 20 + wq * 4]) = vh;
        *reinterpret_cast<uint4*>(&WsL[wrow * 20 + wq * 4]) = vl;
        __syncthreads();
        if (c < 15) {
            int k0 = (c + 1) * 32;
            if (aact) fa = *reinterpret_cast<const float4*>(A + (size_t)(r0 + ar) * ldA + k0 + aq * 4);
            vh = *reinterpret_cast<const uint4*>(Wh + (size_t)(c0 + wrow) * 512 + k0 + wq * 8);
            vl = *reinterpret_cast<const uint4*>(Wl + (size_t)(c0 + wrow) * 512 + k0 + wq * 8);
        }
#pragma unroll
        for (int ks = 0; ks < 2; ks++) {
            unsigned aH[4], aL[4], bH[2], bL[2];
            aH[0] = AsH[g * 20 + ks * 8 + tg];       aH[1] = AsH[(g + 8) * 20 + ks * 8 + tg];
            aH[2] = AsH[g * 20 + ks * 8 + tg + 4];   aH[3] = AsH[(g + 8) * 20 + ks * 8 + tg + 4];
            aL[0] = AsL[g * 20 + ks * 8 + tg];       aL[1] = AsL[(g + 8) * 20 + ks * 8 + tg];
            aL[2] = AsL[g * 20 + ks * 8 + tg + 4];   aL[3] = AsL[(g + 8) * 20 + ks * 8 + tg + 4];
            int n = wid * 8 + g;
            bH[0] = WsH[n * 20 + ks * 8 + tg]; bH[1] = WsH[n * 20 + ks * 8 + tg + 4];
            bL[0] = WsL[n * 20 + ks * 8 + tg]; bL[1] = WsL[n * 20 + ks * 8 + tg + 4];
            mma_bf16(acc, aH, bH);
            mma_bf16(acc, aL, bH);
            mma_bf16(acc, aH, bL);
        }
        __syncthreads();
    }
}

// ---------------- persistent sequential recurrence ----------------
__global__ __launch_bounds__(256, 1) void recur_k(
    const bf16* __restrict__ WGh, const bf16* __restrict__ WGl,
    const float* __restrict__ P, const float* __restrict__ bhh,
    const bf16* __restrict__ W0hh, const bf16* __restrict__ W0hl, const float* __restrict__ PE,
    const bf16* __restrict__ W1h, const bf16* __restrict__ W1l, const float* __restrict__ b1,
    const bf16* __restrict__ W2h, const bf16* __restrict__ W2l, const float* __restrict__ b2p,
    const float* __restrict__ eps, float* __restrict__ qmu, float* __restrict__ qstd,
    bf16* __restrict__ stbf, float* __restrict__ carryA, float* __restrict__ carryB,
    const float* __restrict__ zeroc, float* __restrict__ y1, float* __restrict__ y2)
{
    __shared__ __align__(16) unsigned SM[6400];
    int b = blockIdx.x, tid = threadIdx.x, lane = tid & 31, wid = tid >> 5;
    int g = lane >> 2, tg = lane & 3;

    for (int t = 0; t < TT; t++) {
        const float* cin = (t == 0) ? zeroc : ((t & 1) ? carryB : carryA);
        float* cout = ((t + 1) & 1) ? carryB : carryA;
        bf16* st_t = stbf + (size_t)t * BB * STATED;
        const float* P_t = P + (size_t)t * BB * 1536;
        const float* PE_t = PE + (size_t)t * BB * FEATD;
        const float* eps_t = eps + (size_t)t * BB * STOCHD;

        // ===== GRU: [256 x 2048] gate GEMM, K=576, tile 32x128 per block =====
        {
            int bx = b & 15, by = b >> 4;
            int r0 = by * 32, c0 = bx * 128;
            int wr = wid >> 2, wc = wid & 3;
            unsigned* AsH = SM;         unsigned* AsL = SM + 640;
            unsigned* WsH = SM + 1280;  unsigned* WsL = SM + 3840;
            float acc[4][4];
#pragma unroll
            for (int nt = 0; nt < 4; nt++)
#pragma unroll
                for (int q = 0; q < 4; q++) acc[nt][q] = 0.f;

            int ar = tid >> 3, aq = tid & 7;
            float4 fa = *reinterpret_cast<const float4*>(cin + (size_t)(r0 + ar) * STATED + aq * 4);
            uint4 vh[2], vl[2];
#pragma unroll
            for (int i = 0; i < 2; i++) {
                int u = tid + i * 256, rw = u >> 2, q = u & 3;
                vh[i] = *reinterpret_cast<const uint4*>(WGh + (size_t)(c0 + rw) * 576 + q * 8);
                vl[i] = *reinterpret_cast<const uint4*>(WGl + (size_t)(c0 + rw) * 576 + q * 8);
            }
            for (int c = 0; c < 18; c++) {
                {
                    unsigned h0, l0, h1, l1;
                    split2(fa.x, fa.y, h0, l0); split2(fa.z, fa.w, h1, l1);
                    AsH[ar * 20 + aq * 2] = h0; AsH[ar * 20 + aq * 2 + 1] = h1;
                    AsL[ar * 20 + aq * 2] = l0; AsL[ar * 20 + aq * 2 + 1] = l1;
                }
#pragma unroll
                for (int i = 0; i < 2; i++) {
                    int u = tid + i * 256, rw = u >> 2, q = u & 3;
                    *reinterpret_cast<uint4*>(&WsH[rw * 20 + q * 4]) = vh[i];
                    *reinterpret_cast<uint4*>(&WsL[rw * 20 + q * 4]) = vl[i];
                }
                __syncthreads();
                if (c < 17) {
                    int k0 = (c + 1) * 32;
                    fa = *reinterpret_cast<const float4*>(cin + (size_t)(r0 + ar) * STATED + k0 + aq * 4);
#pragma unroll
                    for (int i = 0; i < 2; i++) {
                        int u = tid + i * 256, rw = u >> 2, q = u & 3;
                        vh[i] = *reinterpret_cast<const uint4*>(WGh + (size_t)(c0 + rw) * 576 + k0 + q * 8);
                        vl[i] = *reinterpret_cast<const uint4*>(WGl + (size_t)(c0 + rw) * 576 + k0 + q * 8);
                    }
                }
#pragma unroll
                for (int ks = 0; ks < 2; ks++) {
                    unsigned aH[4], aL[4];
                    int r = wr * 16 + g;
                    aH[0] = AsH[r * 20 + ks * 8 + tg];     aH[1] = AsH[(r + 8) * 20 + ks * 8 + tg];
                    aH[2] = AsH[r * 20 + ks * 8 + tg + 4]; aH[3] = AsH[(r + 8) * 20 + ks * 8 + tg + 4];
                    aL[0] = AsL[r * 20 + ks * 8 + tg];     aL[1] = AsL[(r + 8) * 20 + ks * 8 + tg];
                    aL[2] = AsL[r * 20 + ks * 8 + tg + 4]; aL[3] = AsL[(r + 8) * 20 + ks * 8 + tg + 4];
#pragma unroll
                    for (int nt = 0; nt < 4; nt++) {
                        int n = wc * 32 + nt * 8 + g;
                        unsigned bH[2] = { WsH[n * 20 + ks * 8 + tg], WsH[n * 20 + ks * 8 + tg + 4] };
                        unsigned bL[2] = { WsL[n * 20 + ks * 8 + tg], WsL[n * 20 + ks * 8 + tg + 4] };
                        mma_bf16(acc[nt], aH, bH);
                        mma_bf16(acc[nt], aL, bH);
                        mma_bf16(acc[nt], aH, bL);
                    }
                }
                __syncthreads();
            }
            // stage raw gates into smem, then block-local GRU epilogue
            float* Cst = (float*)SM;   // 32 x 132
#pragma unroll
            for (int nt = 0; nt < 4; nt++) {
                int cc = wc * 32 + nt * 8 + tg * 2;
                int rr = wr * 16 + g;
                Cst[rr * 132 + cc]           = acc[nt][0];
                Cst[rr * 132 + cc + 1]       = acc[nt][1];
                Cst[(rr + 8) * 132 + cc]     = acc[nt][2];
                Cst[(rr + 8) * 132 + cc + 1] = acc[nt][3];
            }
            __syncthreads();
#pragma unroll
            for (int i = 0; i < 4; i++) {
                int o = tid + i * 256;
                int row = o >> 5, jl = o & 31;
                int gr = r0 + row, j = bx * 32 + jl;
                float rv = Cst[row * 132 + jl];
                float zv = Cst[row * 132 + 32 + jl];
                float nsv = Cst[row * 132 + 64 + jl];
                float nhv = Cst[row * 132 + 96 + jl];
                float rr_ = sigmoidf_(rv + P_t[(size_t)gr * 1536 + j]);
                float zz = sigmoidf_(zv + P_t[(size_t)gr * 1536 + 512 + j]);
                float nn = tanhf(nsv + P_t[(size_t)gr * 1536 + 1024 + j] + rr_ * (nhv + bhh[1024 + j]));
                float hp = cin[(size_t)gr * STATED + 64 + j];
                float h = (1.f - zz) * nn + zz * hp;
                cout[(size_t)gr * STATED + 64 + j] = h;
                st_t[(size_t)gr * STATED + j] = __float2bfloat16(h);
            }
        }
        gbar();

        // ===== L0: y1 = elu(h @ W0h^T + PE_t)  [256x512], K=512 =====
        {
            int by = b >> 3, bx = b & 7;
            int r0 = by * 16, c0 = bx * 64;
            float acc[4];
            gemm16(cout + 64, STATED, W0hh, W0hl, r0, c0, acc, SM, tid, wid, g, tg);
            int cc = c0 + wid * 8 + tg * 2;
            int gr = r0 + g;
            y1[(size_t)gr * 512 + cc]           = eluf(acc[0] + PE_t[(size_t)gr * 512 + cc]);
            y1[(size_t)gr * 512 + cc + 1]       = eluf(acc[1] + PE_t[(size_t)gr * 512 + cc + 1]);
            y1[(size_t)(gr + 8) * 512 + cc]     = eluf(acc[2] + PE_t[(size_t)(gr + 8) * 512 + cc]);
            y1[(size_t)(gr + 8) * 512 + cc + 1] = eluf(acc[3] + PE_t[(size_t)(gr + 8) * 512 + cc + 1]);
        }
        gbar();

        // ===== L1: y2 = elu(y1 @ W1^T + b1) =====
        {
            int by = b >> 3, bx = b & 7;
            int r0 = by * 16, c0 = bx * 64;
            float acc[4];
            gemm16(y1, 512, W1h, W1l, r0, c0, acc, SM, tid, wid, g, tg);
            int cc = c0 + wid * 8 + tg * 2;
            int gr = r0 + g;
            y2[(size_t)gr * 512 + cc]           = eluf(acc[0] + b1[cc]);
            y2[(size_t)gr * 512 + cc + 1]       = eluf(acc[1] + b1[cc + 1]);
            y2[(size_t)(gr + 8) * 512 + cc]     = eluf(acc[2] + b1[cc]);
            y2[(size_t)(gr + 8) * 512 + cc + 1] = eluf(acc[3] + b1[cc + 1]);
        }
        gbar();

        // ===== L2 + sample: qraw[256x128] (interleaved mu/std), K=512 =====
        if (b < 32) {
            int by = b >> 1, bx = b & 1;
            int r0 = by * 16, c0 = bx * 64;
            float acc[4];
            gemm16(y2, 512, W2h, W2l, r0, c0, acc, SM, tid, wid, g, tg);
            int cc = c0 + wid * 8 + tg * 2;
            int i_ = cc >> 1;
#pragma unroll
            for (int rr = 0; rr < 2; rr++) {
                int gr = r0 + g + rr * 8;
                float mu = acc[rr * 2] + b2p[cc];
                float sd = softplusf(acc[rr * 2 + 1] + b2p[cc + 1]) + 1e-4f;
                float s = fmaf(sd, eps_t[(size_t)gr * 64 + i_], mu);
                qmu[(size_t)(t * BB + gr) * 64 + i_] = mu;
                qstd[(size_t)(t * BB + gr) * 64 + i_] = sd;
                cout[(size_t)gr * STATED + i_] = s;
                st_t[(size_t)gr * STATED + 512 + i_] = __float2bfloat16(s);
            }
        }
        gbar();
    }
}

// ---------------- misc ----------------
__global__ void e0_l1(const float* __restrict__ ep_b0, const float* __restrict__ ep_W1,
                      const float* __restrict__ ep_b1, float* __restrict__ l1)
{
    __shared__ float x0[512];
    for (int k = threadIdx.x; k < 512; k += 256) x0[k] = eluf(ep_b0[k]);
    __syncthreads();
    for (int o = threadIdx.x; o < 512; o += 256) {
        float v = ep_b1[o];
        for (int k = 0; k < 512; k++) v = fmaf(x0[k], ep_W1[(size_t)o * 512 + k], v);
        l1[o] = eluf(v);
    }
}

__global__ void e0_head(const float* __restrict__ l1, const float* __restrict__ ep_W2,
                        const float* __restrict__ ep_b2, float* __restrict__ e0)
{
    int o = blockIdx.x * 256 + threadIdx.x;
    float v = ep_b2[o];
    for (int k = 0; k < 512; k++) v = fmaf(l1[k], ep_W2[(size_t)o * 512 + k], v);
    e0[o] = v;
}

__global__ void build_pcat(const bf16* __restrict__ stbf, const bf16* __restrict__ Ebf,
                           const bf16* __restrict__ e0bf, bf16* __restrict__ out)
{
    int r = blockIdx.x;
    const bf16* src = (r < 256) ? e0bf : (Ebf + (size_t)(r - 256) * EMBD);
    bf16* o = out + (size_t)r * 1536;
    const bf16* st = stbf + (size_t)r * STATED;
    for (int c = threadIdx.x; c < 1536; c += 256)
        o[c] = (c < 512) ? st[c] : src[c - 512];
}

// ---------------- reductions ----------------
__global__ void zero_acc_k(double* acc) { if (threadIdx.x < 3) acc[threadIdx.x] = 0.0; }

__global__ void kl_reduce_k(const float* __restrict__ praw, const float* __restrict__ qmu,
                            const float* __restrict__ qstd, double* __restrict__ acc)
{
    __shared__ double sh[256];
    double s = 0.0;
    long total = (long)TBD * STOCHD;
    for (long idx = blockIdx.x * (long)blockDim.x + threadIdx.x; idx < total;
         idx += (long)gridDim.x * blockDim.x) {
        int r = (int)(idx >> 6), i = (int)(idx & 63);
        float pmu = praw[(size_t)r * 128 + i];
        float psd = softplusf(praw[(size_t)r * 128 + 64 + i]) + 1e-4f;
        float qm = qmu[idx], qs = qstd[idx];
        float d = qm - pmu;
        s += (double)(logf(psd / qs) + (qs * qs + d * d) / (2.f * psd * psd) - 0.5f);
    }
    sh[threadIdx.x] = s; __syncthreads();
    for (int o = 128; o > 0; o >>= 1) {
        if (threadIdx.x < o) sh[threadIdx.x] += sh[threadIdx.x + o];
        __syncthreads();
    }
    if (threadIdx.x == 0) atomicAdd(acc, sh[0]);
}

__global__ void emb_reduce_k(const float* __restrict__ emb, const float* __restrict__ embmu,
                             double* __restrict__ acc)
{
    __shared__ double sh[256];
    double s = 0.0;
    long total = (long)TBD * EMBD;
    for (long idx = blockIdx.x * (long)blockDim.x + threadIdx.x; idx < total;
         idx += (long)gridDim.x * blockDim.x) {
        float d = emb[idx] - embmu[idx];
        s += (double)(0.5f * d * d + 0.5f * LOG2PI_F);
    }
    sh[threadIdx.x] = s; __syncthreads();
    for (int o = 128; o > 0; o >>= 1) {
        if (threadIdx.x < o) sh[threadIdx.x] += sh[threadIdx.x + o];
        __syncthreads();
    }
    if (threadIdx.x == 0) atomicAdd(acc, sh[0]);
}

__global__ void reward_reduce_k(const bf16* __restrict__ big2, const float* __restrict__ W,
                                const float* __restrict__ bias, const float* __restrict__ reward,
                                double* __restrict__ acc)
{
    __shared__ double sh[8];
    int lane = threadIdx.x & 31, wib = threadIdx.x >> 5;
    int gwarp = (blockIdx.x * blockDim.x + threadIdx.x) >> 5;
    int nwarps = (gridDim.x * blockDim.x) >> 5;
    double local = 0.0;
    for (int r = gwarp; r < TBD; r += nwarps) {
        float sum = 0.f;
        const bf16* row = big2 + (size_t)r * FEATD;
        for (int k = lane; k < FEATD; k += 32)
            sum = fmaf(__bfloat162float(row[k]), W[k], sum);
#pragma unroll
        for (int o = 16; o > 0; o >>= 1) sum += __shfl_xor_sync(0xffffffffu, sum, o);
        if (lane == 0) {
            float d = reward[r] - (sum + bias[0]);
            local += (double)(0.5f * d * d + 0.5f * LOG2PI_F);
        }
    }
    if (lane == 0) sh[wib] = local;
    __syncthreads();
    if (threadIdx.x == 0) {
        double t = 0.0;
        for (int i = 0; i < 8; i++) t += sh[i];
        atomicAdd(acc, t);
    }
}

__global__ void finalize_k(const double* __restrict__ acc, float* __restrict__ out, int n) {
    double inv = 1.0 / (double)(TT * BB);
    float loss = (float)((acc[0] + acc[1] + acc[2]) * inv);
    for (int i = 0; i < n; i++) out[i] = loss;
}

// ---------------- host ----------------
static void* symaddr(const void* sym) {
    void* p = nullptr;
    cudaGetSymbolAddress(&p, sym);
    return p;
}

extern "C" void kernel_launch(void* const* d_in, const int* in_sizes, int n_in,
                              void* d_out, int out_size)
{
    const float* emb     = (const float*)d_in[0];
    const float* action  = (const float*)d_in[1];
    const float* reward  = (const float*)d_in[2];
    const float* eps     = (const float*)d_in[3];
    const float* gru_Wih = (const float*)d_in[4];
    const float* gru_bih = (const float*)d_in[5];
    const float* gru_Whh = (const float*)d_in[6];
    const float* gru_bhh = (const float*)d_in[7];
    const float* st_W0 = (const float*)d_in[8];  const float* st_b0 = (const float*)d_in[9];
    const float* st_W1 = (const float*)d_in[10]; const float* st_b1 = (const float*)d_in[11];
    const float* st_W2 = (const float*)d_in[12]; const float* st_b2 = (const float*)d_in[13];
    const float* ep_W0 = (const float*)d_in[14]; const float* ep_b0 = (const float*)d_in[15];
    const float* ep_W1 = (const float*)d_in[16]; const float* ep_b1 = (const float*)d_in[17];
    const float* ep_W2 = (const float*)d_in[18]; const float* ep_b2 = (const float*)d_in[19];
    const float* rp_W0 = (const float*)d_in[20]; const float* rp_b0 = (const float*)d_in[21];
    const float* rp_W1 = (const float*)d_in[22]; const float* rp_b1 = (const float*)d_in[23];
    const float* rp_W2 = (const float*)d_in[24]; const float* rp_b2 = (const float*)d_in[25];

    float* carryA = (float*)symaddr(g_carryA);
    float* carryB = (float*)symaddr(g_carryB);
    float* zeroc  = (float*)symaddr(g_zeroc);
    float* y1     = (float*)symaddr(g_y1);
    float* y2     = (float*)symaddr(g_y2);
    float* qmu    = (float*)symaddr(g_qmu);
    float* qstd   = (float*)symaddr(g_qstd);
    float* P      = (float*)symaddr(g_P);
    float* PE     = (float*)symaddr(g_PE);
    float* E      = (float*)symaddr(g_E);
    float* praw   = (float*)symaddr(g_praw);
    float* e0     = (float*)symaddr(g_e0);
    float* e0l1   = (float*)symaddr(g_e0l1);
    float* b2p    = (float*)symaddr(g_b2p);
    double* acc   = (double*)symaddr(g_acc);
    bf16* stbf   = (bf16*)symaddr(g_states_bf);
    bf16* embbf  = (bf16*)symaddr(g_emb_bf);
    bf16* Ebf    = (bf16*)symaddr(g_E_bf);
    bf16* pcatbf = (bf16*)symaddr(g_pcat_bf);
    bf16* big1bf = (bf16*)symaddr(g_big1_bf);
    bf16* big2bf = (bf16*)symaddr(g_big2_bf);
    bf16* e0bf   = (bf16*)symaddr(g_e0_bf);
    bf16* stW0b  = (bf16*)symaddr(g_stW0b);
    bf16* stW1b  = (bf16*)symaddr(g_stW1b);
    bf16* stW2b  = (bf16*)symaddr(g_stW2b);
    bf16* epW0b  = (bf16*)symaddr(g_epW0b);
    bf16* epW1b  = (bf16*)symaddr(g_epW1b);
    bf16* epW2b  = (bf16*)symaddr(g_epW2b);
    bf16* rpW0b  = (bf16*)symaddr(g_rpW0b);
    bf16* rpW1b  = (bf16*)symaddr(g_rpW1b);
    bf16* WGh  = (bf16*)symaddr(g_WGh);   bf16* WGl  = (bf16*)symaddr(g_WGl);
    bf16* W0hh = (bf16*)symaddr(g_W0hh);  bf16* W0hl = (bf16*)symaddr(g_W0hl);
    bf16* W1h  = (bf16*)symaddr(g_W1h);   bf16* W1l  = (bf16*)symaddr(g_W1l);
    bf16* W2h  = (bf16*)symaddr(g_W2h);   bf16* W2l  = (bf16*)symaddr(g_W2l);

    zero_acc_k<<<1, 32>>>(acc);

    // conversions + prep
    cvt_bf_k<<<2048, 256>>>(emb,   embbf, (long)TBD * EMBD);
    cvt_bf_k<<<512, 256>>>(st_W0, stW0b, 512L * 1536);
    cvt_bf_k<<<256, 256>>>(st_W1, stW1b, 512L * 512);
    cvt_bf_k<<<64,  256>>>(st_W2, stW2b, 128L * 512);
    cvt_bf_k<<<256, 256>>>(ep_W0, epW0b, 512L * 576);
    cvt_bf_k<<<256, 256>>>(ep_W1, epW1b, 512L * 512);
    cvt_bf_k<<<512, 256>>>(ep_W2, epW2b, 1024L * 512);
    cvt_bf_k<<<256, 256>>>(rp_W0, rpW0b, 512L * 576);
    cvt_bf_k<<<256, 256>>>(rp_W1, rpW1b, 512L * 512);
    prep_P<<<TBD, 256>>>(action, gru_Wih, gru_bih, gru_bhh, P);
    prep_WG<<<1024, 256>>>(gru_Wih, gru_Whh, WGh, WGl);
    prep_split<<<256, 256>>>(st_W0, 1536, 512, W0hh, W0hl, 512L * 512);
    prep_split<<<256, 256>>>(st_W1, 512, 512, W1h, W1l, 512L * 512);
    prep_W2p<<<64, 256>>>(st_W2, st_b2, W2h, W2l, b2p);
    e0_l1<<<1, 256>>>(ep_b0, ep_W1, ep_b1, e0l1);
    e0_head<<<4, 256>>>(e0l1, ep_W2, ep_b2, e0);
    cvt_bf_k<<<4, 256>>>(e0, e0bf, EMBD);

    // PE = emb_prev @ st_W0[:,512:1536]^T + st_b0   (tensor core, rowShift)
    mma_gemm<0, true, true, false><<<dim3(4, 128), 256>>>(
        embbf, EMBD, stW0b + 512, 1536, st_b0, PE, nullptr, FEATD, EMBD);

    // sequential recurrence: persistent, split-bf16 tensor-core stages
    recur_k<<<NBLK, 256>>>(WGh, WGl, P, gru_bhh, W0hh, W0hl, PE,
                           W1h, W1l, st_b1, W2h, W2l, b2p,
                           eps, qmu, qstd, stbf, carryA, carryB, zeroc, y1, y2);

    // shared ep-MLP: E = ep_mlp(states) = emb_mu; row-shifted = pre_emb
    mma_gemm<1, false, false, true><<<dim3(4, 128), 256>>>(
        stbf, STATED, epW0b, STATED, ep_b0, nullptr, big1bf, FEATD, STATED);
    mma_gemm<1, false, false, true><<<dim3(4, 128), 256>>>(
        big1bf, FEATD, epW1b, FEATD, ep_b1, nullptr, big2bf, FEATD, FEATD);
    mma_gemm<0, false, true, true><<<dim3(8, 128), 256>>>(
        big2bf, FEATD, epW2b, FEATD, ep_b2, E, Ebf, EMBD, FEATD);

    // prior path
    build_pcat<<<TBD, 256>>>(stbf, Ebf, e0bf, pcatbf);
    mma_gemm<1, false, false, true><<<dim3(4, 128), 256>>>(
        pcatbf, 1536, stW0b, 1536, st_b0, nullptr, big1bf, FEATD, 1536);
    mma_gemm<1, false, false, true><<<dim3(4, 128), 256>>>(
        big1bf, FEATD, stW1b, FEATD, st_b1, nullptr, big2bf, FEATD, FEATD);
    mma_gemm<0, false, true, false><<<dim3(1, 128), 256>>>(
        big2bf, FEATD, stW2b, FEATD, st_b2, praw, nullptr, 128, FEATD);
    kl_reduce_k<<<1024, 256>>>(praw, qmu, qstd, acc + 0);

    // emb loss
    emb_reduce_k<<<2048, 256>>>(emb, E, acc + 1);

    // reward loss
    mma_gemm<1, false, false, true><<<dim3(4, 128), 256>>>(
        stbf, STATED, rpW0b, STATED, rp_b0, nullptr, big1bf, FEATD, STATED);
    mma_gemm<1, false, false, true><<<dim3(4, 128), 256>>>(
        big1bf, FEATD, rpW1b, FEATD, rp_b1, nullptr, big2bf, FEATD, FEATD);
    reward_reduce_k<<<512, 256>>>(big2bf, rp_W2, rp_b2, reward, acc + 2);

    finalize_k<<<1, 1>>>(acc, (float*)d_out, out_size);
}

// round 7
// speedup vs baseline: 1.8448x; 1.0005x over previous
#include <cuda_runtime.h>
#include <cuda_bf16.h>
#include <math.h>

#define TT 64
#define BB 256
#define EMBD 1024
#define ADIM 6
#define STOCHD 64
#define HIDD 512
#define FEATD 512
#define STATED 576
#define TBD (TT*BB)
#define NBLK 128
#define LOG2PI_F 1.837877066409345483560659472811f

typedef __nv_bfloat16 bf16;

// ---------------- scratch ----------------
__device__ float g_carryA[BB*STATED];   // [s(64)|h(512)]
__device__ float g_carryB[BB*STATED];
__device__ float g_zeroc[BB*STATED];
__device__ float g_y1[BB*FEATD];
__device__ float g_y2[BB*FEATD];
__device__ float g_qmu[TBD*STOCHD];
__device__ float g_qstd[TBD*STOCHD];
__device__ float g_P[TBD*1536];
__device__ float g_PE[TBD*FEATD];
__device__ float g_E[TBD*EMBD];
__device__ float g_praw[TBD*2*STOCHD];
__device__ float g_e0[EMBD];
__device__ float g_e0l1[FEATD];
__device__ float g_b2p[128];
__device__ double g_acc[3];
__device__ unsigned g_bcount = 0;
__device__ unsigned g_bgen = 0;

__device__ bf16 g_states_bf[TBD*STATED];
__device__ bf16 g_emb_bf[TBD*EMBD];
__device__ bf16 g_E_bf[TBD*EMBD];
__device__ bf16 g_pcat_bf[TBD*1536];
__device__ bf16 g_big1_bf[TBD*FEATD];
__device__ bf16 g_big2_bf[TBD*FEATD];
__device__ bf16 g_e0_bf[EMBD];
__device__ bf16 g_stW0b[512*1536];
__device__ bf16 g_stW1b[512*512];
__device__ bf16 g_stW2b[128*512];
__device__ bf16 g_epW0b[512*576];
__device__ bf16 g_epW1b[512*512];
__device__ bf16 g_epW2b[1024*512];
__device__ bf16 g_rpW0b[512*576];
__device__ bf16 g_rpW1b[512*512];
// split hi/lo weights for the sequential path
__device__ bf16 g_WGh[2048*576];
__device__ bf16 g_WGl[2048*576];
__device__ bf16 g_W0hh[512*512];
__device__ bf16 g_W0hl[512*512];
__device__ bf16 g_W1h[512*512];
__device__ bf16 g_W1l[512*512];
__device__ bf16 g_W2h[128*512];
__device__ bf16 g_W2l[128*512];

// ---------------- math ----------------
__device__ __forceinline__ float softplusf(float x) {
    return fmaxf(x, 0.f) + log1pf(expf(-fabsf(x)));
}
__device__ __forceinline__ float sigmoidf_(float x) { return 1.f / (1.f + expf(-x)); }
__device__ __forceinline__ float eluf(float x) { return x > 0.f ? x : expm1f(x); }
template<int ACT> __device__ __forceinline__ float actf(float v) {
    if (ACT == 1) return eluf(v);
    return v;
}

__device__ __forceinline__ void mma_bf16(float* c, const unsigned* a, const unsigned* b) {
    asm volatile(
        "mma.sync.aligned.m16n8k16.row.col.f32.bf16.bf16.f32 "
        "{%0,%1,%2,%3},{%4,%5,%6,%7},{%8,%9},{%0,%1,%2,%3};"
        : "+f"(c[0]), "+f"(c[1]), "+f"(c[2]), "+f"(c[3])
        : "r"(a[0]), "r"(a[1]), "r"(a[2]), "r"(a[3]), "r"(b[0]), "r"(b[1]));
}

// split two f32 into packed bf16 hi-word and lo-word (k-consecutive pair)
__device__ __forceinline__ void split2(float x, float y, unsigned& h, unsigned& l) {
    bf16 hx = __float2bfloat16(x), hy = __float2bfloat16(y);
    bf16 lx = __float2bfloat16(x - __bfloat162float(hx));
    bf16 ly = __float2bfloat16(y - __bfloat162float(hy));
    h = ((unsigned)__bfloat16_as_ushort(hy) << 16) | __bfloat16_as_ushort(hx);
    l = ((unsigned)__bfloat16_as_ushort(ly) << 16) | __bfloat16_as_ushort(lx);
}

// ---------------- grid barrier ----------------
__device__ __forceinline__ void gbar() {
    __threadfence();
    __syncthreads();
    if (threadIdx.x == 0) {
        unsigned gen = atomicAdd(&g_bgen, 0u);
        if (atomicAdd(&g_bcount, 1u) == NBLK - 1u) {
            g_bcount = 0u;
            __threadfence();
            atomicAdd(&g_bgen, 1u);
        } else {
            while (atomicAdd(&g_bgen, 0u) == gen) { __nanosleep(32); }
        }
    }
    __syncthreads();
}

// ---------------- bf16 tensor-core GEMM (batched; proven in R4) ----------------
template<int ACT, bool ROWSHIFT, bool WF32, bool WBF>
__global__ __launch_bounds__(256, 2) void mma_gemm(
    const bf16* __restrict__ A, int ldA,
    const bf16* __restrict__ W, int ldW,
    const float* __restrict__ bias,
    float* __restrict__ Cf, bf16* __restrict__ Cb, int ldC, int K)
{
    __shared__ __align__(16) unsigned As[2][128 * 20];
    __shared__ __align__(16) unsigned Ws[2][128 * 20];
    int tid = threadIdx.x, lane = tid & 31, wid = tid >> 5;
    int g = lane >> 2, tg = lane & 3;
    int wr = wid >> 2, wc = wid & 3;
    int row0 = blockIdx.y * 128, col0 = blockIdx.x * 128;

    float acc[4][4][4];
#pragma unroll
    for (int mt = 0; mt < 4; mt++)
#pragma unroll
        for (int nt = 0; nt < 4; nt++)
#pragma unroll
            for (int q = 0; q < 4; q++) acc[mt][nt][q] = 0.f;

    const int nc = K / 32;
    uint4 pa[2], pb[2];
#pragma unroll
    for (int i = 0; i < 2; i++) {
        int u = tid + i * 256, row = u >> 2, q = u & 3;
        int grow = row0 + row;
        if (ROWSHIFT && grow >= 256) grow -= 256;
        pa[i] = *reinterpret_cast<const uint4*>(A + (size_t)grow * ldA + q * 8);
        pb[i] = *reinterpret_cast<const uint4*>(W + (size_t)(col0 + row) * ldW + q * 8);
    }
#pragma unroll
    for (int i = 0; i < 2; i++) {
        int u = tid + i * 256, row = u >> 2, q = u & 3;
        *reinterpret_cast<uint4*>(&As[0][row * 20 + q * 4]) = pa[i];
        *reinterpret_cast<uint4*>(&Ws[0][row * 20 + q * 4]) = pb[i];
    }
    __syncthreads();

    int buf = 0;
    for (int c = 0; c < nc; c++) {
        bool nxt = (c + 1 < nc);
        if (nxt) {
            int k0 = (c + 1) * 32;
#pragma unroll
            for (int i = 0; i < 2; i++) {
                int u = tid + i * 256, row = u >> 2, q = u & 3;
                int grow = row0 + row;
                if (ROWSHIFT && grow >= 256) grow -= 256;
                pa[i] = *reinterpret_cast<const uint4*>(A + (size_t)grow * ldA + k0 + q * 8);
                pb[i] = *reinterpret_cast<const uint4*>(W + (size_t)(col0 + row) * ldW + k0 + q * 8);
            }
        }
        const unsigned* as = As[buf];
        const unsigned* ws = Ws[buf];
#pragma unroll
        for (int ks = 0; ks < 2; ks++) {
            unsigned af[4][4], bfr[4][2];
#pragma unroll
            for (int mt = 0; mt < 4; mt++) {
                int r = wr * 64 + mt * 16 + g;
                af[mt][0] = as[r * 20 + ks * 8 + tg];
                af[mt][1] = as[(r + 8) * 20 + ks * 8 + tg];
                af[mt][2] = as[r * 20 + ks * 8 + tg + 4];
                af[mt][3] = as[(r + 8) * 20 + ks * 8 + tg + 4];
            }
#pragma unroll
            for (int nt = 0; nt < 4; nt++) {
                int n = wc * 32 + nt * 8 + g;
                bfr[nt][0] = ws[n * 20 + ks * 8 + tg];
                bfr[nt][1] = ws[n * 20 + ks * 8 + tg + 4];
            }
#pragma unroll
            for (int mt = 0; mt < 4; mt++)
#pragma unroll
                for (int nt = 0; nt < 4; nt++)
                    mma_bf16(acc[mt][nt], af[mt], bfr[nt]);
        }
        if (nxt) {
            int nb = buf ^ 1;
#pragma unroll
            for (int i = 0; i < 2; i++) {
                int u = tid + i * 256, row = u >> 2, q = u & 3;
                *reinterpret_cast<uint4*>(&As[nb][row * 20 + q * 4]) = pa[i];
                *reinterpret_cast<uint4*>(&Ws[nb][row * 20 + q * 4]) = pb[i];
            }
        }
        __syncthreads();
        buf ^= 1;
    }

#pragma unroll
    for (int mt = 0; mt < 4; mt++) {
        int r = row0 + wr * 64 + mt * 16 + g;
#pragma unroll
        for (int nt = 0; nt < 4; nt++) {
            int cc = col0 + wc * 32 + nt * 8 + tg * 2;
            float b0v = bias[cc], b1v = bias[cc + 1];
            float v00 = actf<ACT>(acc[mt][nt][0] + b0v);
            float v01 = actf<ACT>(acc[mt][nt][1] + b1v);
            float v10 = actf<ACT>(acc[mt][nt][2] + b0v);
            float v11 = actf<ACT>(acc[mt][nt][3] + b1v);
            if (WF32) {
                Cf[(size_t)r * ldC + cc]           = v00;
                Cf[(size_t)r * ldC + cc + 1]       = v01;
                Cf[(size_t)(r + 8) * ldC + cc]     = v10;
                Cf[(size_t)(r + 8) * ldC + cc + 1] = v11;
            }
            if (WBF) {
                Cb[(size_t)r * ldC + cc]           = __float2bfloat16(v00);
                Cb[(size_t)r * ldC + cc + 1]       = __float2bfloat16(v01);
                Cb[(size_t)(r + 8) * ldC + cc]     = __float2bfloat16(v10);
                Cb[(size_t)(r + 8) * ldC + cc + 1] = __float2bfloat16(v11);
            }
        }
    }
}

// ---------------- prep ----------------
__global__ void cvt_bf_k(const float* __restrict__ s, bf16* __restrict__ d, long n) {
    for (long i = blockIdx.x * (long)blockDim.x + threadIdx.x; i < n;
         i += (long)gridDim.x * blockDim.x)
        d[i] = __float2bfloat16(s[i]);
}

__global__ void prep_P(const float* __restrict__ action, const float* __restrict__ Wih,
                       const float* __restrict__ bih, const float* __restrict__ bhh,
                       float* __restrict__ P)
{
    int r = blockIdx.x;
    __shared__ float a[ADIM];
    if (threadIdx.x < ADIM) a[threadIdx.x] = action[(size_t)r * ADIM + threadIdx.x];
    __syncthreads();
    for (int j = threadIdx.x; j < 1536; j += 256) {
        float v = bih[j];
#pragma unroll
        for (int k = 0; k < ADIM; k++) v = fmaf(a[k], Wih[j * 70 + 64 + k], v);
        if (j < 1024) v += bhh[j];
        P[(size_t)r * 1536 + j] = v;
    }
}

// gate-interleaved packed GRU weights, split hi/lo.
// col c: jb=c>>7, gate=(c>>5)&3, jl=c&31, j=jb*32+jl; gates: 0=r,1=z,2=ns(s only),3=nh(h only)
__global__ void prep_WG(const float* __restrict__ Wih, const float* __restrict__ Whh,
                        bf16* __restrict__ WGh, bf16* __restrict__ WGl)
{
    long total = 2048L * 576;
    for (long idx = blockIdx.x * (long)blockDim.x + threadIdx.x; idx < total;
         idx += (long)gridDim.x * blockDim.x) {
        int c = (int)(idx / 576), k = (int)(idx % 576);
        int jb = c >> 7, gs = (c >> 5) & 3, jl = c & 31, j = jb * 32 + jl;
        float v = 0.f;
        if (gs == 0)      v = (k < 64) ? Wih[j * 70 + k] : Whh[(size_t)j * 512 + k - 64];
        else if (gs == 1) v = (k < 64) ? Wih[(512 + j) * 70 + k] : Whh[(size_t)(512 + j) * 512 + k - 64];
        else if (gs == 2) v = (k < 64) ? Wih[(1024 + j) * 70 + k] : 0.f;
        else              v = (k < 64) ? 0.f : Whh[(size_t)(1024 + j) * 512 + k - 64];
        bf16 h = __float2bfloat16(v);
        WGh[idx] = h;
        WGl[idx] = __float2bfloat16(v - __bfloat162float(h));
    }
}

__global__ void prep_split(const float* __restrict__ src, int ld, int K,
                           bf16* __restrict__ hi, bf16* __restrict__ lo, long n)
{
    for (long idx = blockIdx.x * (long)blockDim.x + threadIdx.x; idx < n;
         idx += (long)gridDim.x * blockDim.x) {
        int row = (int)(idx / K), k = (int)(idx % K);
        float v = src[(size_t)row * ld + k];
        bf16 h = __float2bfloat16(v);
        hi[idx] = h;
        lo[idx] = __float2bfloat16(v - __bfloat162float(h));
    }
}

// W2 rows interleaved (mu_i, std_i) pairs + matching bias
__global__ void prep_W2p(const float* __restrict__ W2, const float* __restrict__ b2,
                         bf16* __restrict__ hi, bf16* __restrict__ lo, float* __restrict__ b2p)
{
    long total = 128L * 512;
    for (long idx = blockIdx.x * (long)blockDim.x + threadIdx.x; idx < total;
         idx += (long)gridDim.x * blockDim.x) {
        int c = (int)(idx / 512), k = (int)(idx % 512);
        int sr = (c & 1) ? (64 + (c >> 1)) : (c >> 1);
        float v = W2[(size_t)sr * 512 + k];
        bf16 h = __float2bfloat16(v);
        hi[idx] = h;
        lo[idx] = __float2bfloat16(v - __bfloat162float(h));
        if (k == 0) b2p[c] = b2[sr];
    }
}

// ---------------- 16x64-tile split-bf16 MMA (K=512) for L0/L1/L2 ----------------
__device__ __forceinline__ void gemm16(
    const float* __restrict__ A, int ldA,
    const bf16* __restrict__ Wh, const bf16* __restrict__ Wl,
    int r0, int c0, float* acc, unsigned* SM,
    int tid, int wid, int g, int tg)
{
    unsigned* AsH = SM;        unsigned* AsL = SM + 320;
    unsigned* WsH = SM + 640;  unsigned* WsL = SM + 1920;
    acc[0] = acc[1] = acc[2] = acc[3] = 0.f;
    int ar = tid >> 3, aq = tid & 7;
    int wrow = tid >> 2, wq = tid & 3;
    bool aact = tid < 128;
    float4 fa = make_float4(0.f, 0.f, 0.f, 0.f);
    uint4 vh, vl;
    if (aact) fa = *reinterpret_cast<const float4*>(A + (size_t)(r0 + ar) * ldA + aq * 4);
    vh = *reinterpret_cast<const uint4*>(Wh + (size_t)(c0 + wrow) * 512 + wq * 8);
    vl = *reinterpret_cast<const uint4*>(Wl + (size_t)(c0 + wrow) * 512 + wq * 8);
    for (int c = 0; c < 16; c++) {
        if (aact) {
            unsigned h0, l0, h1, l1;
            split2(fa.x, fa.y, h0, l0); split2(fa.z, fa.w, h1, l1);
            AsH[ar * 20 + aq * 2] = h0; AsH[ar * 20 + aq * 2 + 1] = h1;
            AsL[ar * 20 + aq * 2] = l0; AsL[ar * 20 + aq * 2 + 1] = l1;
        }
        *reinterpret_cast<uint4*>(&WsH[wrow * 20 + wq * 4]) = vh;
        *reinterpret_cast<uint4*>(&WsL[wrow * 20 + wq * 4]) = vl;
        __syncthreads();
        if (c < 15) {
            int k0 = (c + 1) * 32;
            if (aact) fa = *reinterpret_cast<const float4*>(A + (size_t)(r0 + ar) * ldA + k0 + aq * 4);
            vh = *reinterpret_cast<const uint4*>(Wh + (size_t)(c0 + wrow) * 512 + k0 + wq * 8);
            vl = *reinterpret_cast<const uint4*>(Wl + (size_t)(c0 + wrow) * 512 + k0 + wq * 8);
        }
#pragma unroll
        for (int ks = 0; ks < 2; ks++) {
            unsigned aH[4], aL[4], bH[2], bL[2];
            aH[0] = AsH[g * 20 + ks * 8 + tg];       aH[1] = AsH[(g + 8) * 20 + ks * 8 + tg];
            aH[2] = AsH[g * 20 + ks * 8 + tg + 4];   aH[3] = AsH[(g + 8) * 20 + ks * 8 + tg + 4];
            aL[0] = AsL[g * 20 + ks * 8 + tg];       aL[1] = AsL[(g + 8) * 20 + ks * 8 + tg];
            aL[2] = AsL[g * 20 + ks * 8 + tg + 4];   aL[3] = AsL[(g + 8) * 20 + ks * 8 + tg + 4];
            int n = wid * 8 + g;
            bH[0] = WsH[n * 20 + ks * 8 + tg]; bH[1] = WsH[n * 20 + ks * 8 + tg + 4];
            bL[0] = WsL[n * 20 + ks * 8 + tg]; bL[1] = WsL[n * 20 + ks * 8 + tg + 4];
            mma_bf16(acc, aH, bH);
            mma_bf16(acc, aL, bH);
            mma_bf16(acc, aH, bL);
        }
        __syncthreads();
    }
}

// ---------------- persistent sequential recurrence ----------------
__global__ __launch_bounds__(256, 1) void recur_k(
    const bf16* __restrict__ WGh, const bf16* __restrict__ WGl,
    const float* __restrict__ P, const float* __restrict__ bhh,
    const bf16* __restrict__ W0hh, const bf16* __restrict__ W0hl, const float* __restrict__ PE,
    const bf16* __restrict__ W1h, const bf16* __restrict__ W1l, const float* __restrict__ b1,
    const bf16* __restrict__ W2h, const bf16* __restrict__ W2l, const float* __restrict__ b2p,
    const float* __restrict__ eps, float* __restrict__ qmu, float* __restrict__ qstd,
    bf16* __restrict__ stbf, float* __restrict__ carryA, float* __restrict__ carryB,
    const float* __restrict__ zeroc, float* __restrict__ y1, float* __restrict__ y2)
{
    __shared__ __align__(16) unsigned SM[6400];
    int b = blockIdx.x, tid = threadIdx.x, lane = tid & 31, wid = tid >> 5;
    int g = lane >> 2, tg = lane & 3;

    for (int t = 0; t < TT; t++) {
        const float* cin = (t == 0) ? zeroc : ((t & 1) ? carryB : carryA);
        float* cout = ((t + 1) & 1) ? carryB : carryA;
        bf16* st_t = stbf + (size_t)t * BB * STATED;
        const float* P_t = P + (size_t)t * BB * 1536;
        const float* PE_t = PE + (size_t)t * BB * FEATD;
        const float* eps_t = eps + (size_t)t * BB * STOCHD;

        // ===== GRU: [256 x 2048] gate GEMM, K=576, tile 32x128 per block =====
        {
            int bx = b & 15, by = b >> 4;
            int r0 = by * 32, c0 = bx * 128;
            int wr = wid >> 2, wc = wid & 3;
            unsigned* AsH = SM;         unsigned* AsL = SM + 640;
            unsigned* WsH = SM + 1280;  unsigned* WsL = SM + 3840;
            float acc[4][4];
#pragma unroll
            for (int nt = 0; nt < 4; nt++)
#pragma unroll
                for (int q = 0; q < 4; q++) acc[nt][q] = 0.f;

            int ar = tid >> 3, aq = tid & 7;
            float4 fa = *reinterpret_cast<const float4*>(cin + (size_t)(r0 + ar) * STATED + aq * 4);
            uint4 vh[2], vl[2];
#pragma unroll
            for (int i = 0; i < 2; i++) {
                int u = tid + i * 256, rw = u >> 2, q = u & 3;
                vh[i] = *reinterpret_cast<const uint4*>(WGh + (size_t)(c0 + rw) * 576 + q * 8);
                vl[i] = *reinterpret_cast<const uint4*>(WGl + (size_t)(c0 + rw) * 576 + q * 8);
            }
            for (int c = 0; c < 18; c++) {
                {
                    unsigned h0, l0, h1, l1;
                    split2(fa.x, fa.y, h0, l0); split2(fa.z, fa.w, h1, l1);
                    AsH[ar * 20 + aq * 2] = h0; AsH[ar * 20 + aq * 2 + 1] = h1;
                    AsL[ar * 20 + aq * 2] = l0; AsL[ar * 20 + aq * 2 + 1] = l1;
                }
#pragma unroll
                for (int i = 0; i < 2; i++) {
                    int u = tid + i * 256, rw = u >> 2, q = u & 3;
                    *reinterpret_cast<uint4*>(&WsH[rw * 20 + q * 4]) = vh[i];
                    *reinterpret_cast<uint4*>(&WsL[rw * 20 + q * 4]) = vl[i];
                }
                __syncthreads();
                if (c < 17) {
                    int k0 = (c + 1) * 32;
                    fa = *reinterpret_cast<const float4*>(cin + (size_t)(r0 + ar) * STATED + k0 + aq * 4);
#pragma unroll
                    for (int i = 0; i < 2; i++) {
                        int u = tid + i * 256, rw = u >> 2, q = u & 3;
                        vh[i] = *reinterpret_cast<const uint4*>(WGh + (size_t)(c0 + rw) * 576 + k0 + q * 8);
                        vl[i] = *reinterpret_cast<const uint4*>(WGl + (size_t)(c0 + rw) * 576 + k0 + q * 8);
                    }
                }
#pragma unroll
                for (int ks = 0; ks < 2; ks++) {
                    unsigned aH[4], aL[4];
                    int r = wr * 16 + g;
                    aH[0] = AsH[r * 20 + ks * 8 + tg];     aH[1] = AsH[(r + 8) * 20 + ks * 8 + tg];
                    aH[2] = AsH[r * 20 + ks * 8 + tg + 4]; aH[3] = AsH[(r + 8) * 20 + ks * 8 + tg + 4];
                    aL[0] = AsL[r * 20 + ks * 8 + tg];     aL[1] = AsL[(r + 8) * 20 + ks * 8 + tg];
                    aL[2] = AsL[r * 20 + ks * 8 + tg + 4]; aL[3] = AsL[(r + 8) * 20 + ks * 8 + tg + 4];
#pragma unroll
                    for (int nt = 0; nt < 4; nt++) {
                        int n = wc * 32 + nt * 8 + g;
                        unsigned bH[2] = { WsH[n * 20 + ks * 8 + tg], WsH[n * 20 + ks * 8 + tg + 4] };
                        unsigned bL[2] = { WsL[n * 20 + ks * 8 + tg], WsL[n * 20 + ks * 8 + tg + 4] };
                        mma_bf16(acc[nt], aH, bH);
                        mma_bf16(acc[nt], aL, bH);
                        mma_bf16(acc[nt], aH, bL);
                    }
                }
                __syncthreads();
            }
            // stage raw gates into smem, then block-local GRU epilogue
            float* Cst = (float*)SM;   // 32 x 132
#pragma unroll
            for (int nt = 0; nt < 4; nt++) {
                int cc = wc * 32 + nt * 8 + tg * 2;
                int rr = wr * 16 + g;
                Cst[rr * 132 + cc]           = acc[nt][0];
                Cst[rr * 132 + cc + 1]       = acc[nt][1];
                Cst[(rr + 8) * 132 + cc]     = acc[nt][2];
                Cst[(rr + 8) * 132 + cc + 1] = acc[nt][3];
            }
            __syncthreads();
#pragma unroll
            for (int i = 0; i < 4; i++) {
                int o = tid + i * 256;
                int row = o >> 5, jl = o & 31;
                int gr = r0 + row, j = bx * 32 + jl;
                float rv = Cst[row * 132 + jl];
                float zv = Cst[row * 132 + 32 + jl];
                float nsv = Cst[row * 132 + 64 + jl];
                float nhv = Cst[row * 132 + 96 + jl];
                float rr_ = sigmoidf_(rv + P_t[(size_t)gr * 1536 + j]);
                float zz = sigmoidf_(zv + P_t[(size_t)gr * 1536 + 512 + j]);
                float nn = tanhf(nsv + P_t[(size_t)gr * 1536 + 1024 + j] + rr_ * (nhv + bhh[1024 + j]));
                float hp = cin[(size_t)gr * STATED + 64 + j];
                float h = (1.f - zz) * nn + zz * hp;
                cout[(size_t)gr * STATED + 64 + j] = h;
                st_t[(size_t)gr * STATED + j] = __float2bfloat16(h);
            }
        }
        gbar();

        // ===== L0: y1 = elu(h @ W0h^T + PE_t)  [256x512], K=512 =====
        {
            int by = b >> 3, bx = b & 7;
            int r0 = by * 16, c0 = bx * 64;
            float acc[4];
            gemm16(cout + 64, STATED, W0hh, W0hl, r0, c0, acc, SM, tid, wid, g, tg);
            int cc = c0 + wid * 8 + tg * 2;
            int gr = r0 + g;
            y1[(size_t)gr * 512 + cc]           = eluf(acc[0] + PE_t[(size_t)gr * 512 + cc]);
            y1[(size_t)gr * 512 + cc + 1]       = eluf(acc[1] + PE_t[(size_t)gr * 512 + cc + 1]);
            y1[(size_t)(gr + 8) * 512 + cc]     = eluf(acc[2] + PE_t[(size_t)(gr + 8) * 512 + cc]);
            y1[(size_t)(gr + 8) * 512 + cc + 1] = eluf(acc[3] + PE_t[(size_t)(gr + 8) * 512 + cc + 1]);
        }
        gbar();

        // ===== L1: y2 = elu(y1 @ W1^T + b1) =====
        {
            int by = b >> 3, bx = b & 7;
            int r0 = by * 16, c0 = bx * 64;
            float acc[4];
            gemm16(y1, 512, W1h, W1l, r0, c0, acc, SM, tid, wid, g, tg);
            int cc = c0 + wid * 8 + tg * 2;
            int gr = r0 + g;
            y2[(size_t)gr * 512 + cc]           = eluf(acc[0] + b1[cc]);
            y2[(size_t)gr * 512 + cc + 1]       = eluf(acc[1] + b1[cc + 1]);
            y2[(size_t)(gr + 8) * 512 + cc]     = eluf(acc[2] + b1[cc]);
            y2[(size_t)(gr + 8) * 512 + cc + 1] = eluf(acc[3] + b1[cc + 1]);
        }
        gbar();

        // ===== L2 + sample: qraw[256x128] (interleaved mu/std), K=512 =====
        if (b < 32) {
            int by = b >> 1, bx = b & 1;
            int r0 = by * 16, c0 = bx * 64;
            float acc[4];
            gemm16(y2, 512, W2h, W2l, r0, c0, acc, SM, tid, wid, g, tg);
            int cc = c0 + wid * 8 + tg * 2;
            int i_ = cc >> 1;
#pragma unroll
            for (int rr = 0; rr < 2; rr++) {
                int gr = r0 + g + rr * 8;
                float mu = acc[rr * 2] + b2p[cc];
                float sd = softplusf(acc[rr * 2 + 1] + b2p[cc + 1]) + 1e-4f;
                float s = fmaf(sd, eps_t[(size_t)gr * 64 + i_], mu);
                qmu[(size_t)(t * BB + gr) * 64 + i_] = mu;
                qstd[(size_t)(t * BB + gr) * 64 + i_] = sd;
                cout[(size_t)gr * STATED + i_] = s;
                st_t[(size_t)gr * STATED + 512 + i_] = __float2bfloat16(s);
            }
        }
        gbar();
    }
}

// ---------------- misc ----------------
__global__ void e0_l1(const float* __restrict__ ep_b0, const float* __restrict__ ep_W1,
                      const float* __restrict__ ep_b1, float* __restrict__ l1)
{
    __shared__ float x0[512];
    for (int k = threadIdx.x; k < 512; k += 256) x0[k] = eluf(ep_b0[k]);
    __syncthreads();
    for (int o = threadIdx.x; o < 512; o += 256) {
        float v = ep_b1[o];
        for (int k = 0; k < 512; k++) v = fmaf(x0[k], ep_W1[(size_t)o * 512 + k], v);
        l1[o] = eluf(v);
    }
}

__global__ void e0_head(const float* __restrict__ l1, const float* __restrict__ ep_W2,
                        const float* __restrict__ ep_b2, float* __restrict__ e0)
{
    int o = blockIdx.x * 256 + threadIdx.x;
    float v = ep_b2[o];
    for (int k = 0; k < 512; k++) v = fmaf(l1[k], ep_W2[(size_t)o * 512 + k], v);
    e0[o] = v;
}

__global__ void build_pcat(const bf16* __restrict__ stbf, const bf16* __restrict__ Ebf,
                           const bf16* __restrict__ e0bf, bf16* __restrict__ out)
{
    int r = blockIdx.x;
    const bf16* src = (r < 256) ? e0bf : (Ebf + (size_t)(r - 256) * EMBD);
    bf16* o = out + (size_t)r * 1536;
    const bf16* st = stbf + (size_t)r * STATED;
    for (int c = threadIdx.x; c < 1536; c += 256)
        o[c] = (c < 512) ? st[c] : src[c - 512];
}

// ---------------- reductions ----------------
__global__ void zero_acc_k(double* acc) { if (threadIdx.x < 3) acc[threadIdx.x] = 0.0; }

__global__ void kl_reduce_k(const float* __restrict__ praw, const float* __restrict__ qmu,
                            const float* __restrict__ qstd, double* __restrict__ acc)
{
    __shared__ double sh[256];
    double s = 0.0;
    long total = (long)TBD * STOCHD;
    for (long idx = blockIdx.x * (long)blockDim.x + threadIdx.x; idx < total;
         idx += (long)gridDim.x * blockDim.x) {
        int r = (int)(idx >> 6), i = (int)(idx & 63);
        float pmu = praw[(size_t)r * 128 + i];
        float psd = softplusf(praw[(size_t)r * 128 + 64 + i]) + 1e-4f;
        float qm = qmu[idx], qs = qstd[idx];
        float d = qm - pmu;
        s += (double)(logf(psd / qs) + (qs * qs + d * d) / (2.f * psd * psd) - 0.5f);
    }
    sh[threadIdx.x] = s; __syncthreads();
    for (int o = 128; o > 0; o >>= 1) {
        if (threadIdx.x < o) sh[threadIdx.x] += sh[threadIdx.x + o];
        __syncthreads();
    }
    if (threadIdx.x == 0) atomicAdd(acc, sh[0]);
}

__global__ void emb_reduce_k(const float* __restrict__ emb, const float* __restrict__ embmu,
                             double* __restrict__ acc)
{
    __shared__ double sh[256];
    double s = 0.0;
    long total = (long)TBD * EMBD;
    for (long idx = blockIdx.x * (long)blockDim.x + threadIdx.x; idx < total;
         idx += (long)gridDim.x * blockDim.x) {
        float d = emb[idx] - embmu[idx];
        s += (double)(0.5f * d * d + 0.5f * LOG2PI_F);
    }
    sh[threadIdx.x] = s; __syncthreads();
    for (int o = 128; o > 0; o >>= 1) {
        if (threadIdx.x < o) sh[threadIdx.x] += sh[threadIdx.x + o];
        __syncthreads();
    }
    if (threadIdx.x == 0) atomicAdd(acc, sh[0]);
}

__global__ void reward_reduce_k(const bf16* __restrict__ big2, const float* __restrict__ W,
                                const float* __restrict__ bias, const float* __restrict__ reward,
                                double* __restrict__ acc)
{
    __shared__ double sh[8];
    int lane = threadIdx.x & 31, wib = threadIdx.x >> 5;
    int gwarp = (blockIdx.x * blockDim.x + threadIdx.x) >> 5;
    int nwarps = (gridDim.x * blockDim.x) >> 5;
    double local = 0.0;
    for (int r = gwarp; r < TBD; r += nwarps) {
        float sum = 0.f;
        const bf16* row = big2 + (size_t)r * FEATD;
        for (int k = lane; k < FEATD; k += 32)
            sum = fmaf(__bfloat162float(row[k]), W[k], sum);
#pragma unroll
        for (int o = 16; o > 0; o >>= 1) sum += __shfl_xor_sync(0xffffffffu, sum, o);
        if (lane == 0) {
            float d = reward[r] - (sum + bias[0]);
            local += (double)(0.5f * d * d + 0.5f * LOG2PI_F);
        }
    }
    if (lane == 0) sh[wib] = local;
    __syncthreads();
    if (threadIdx.x == 0) {
        double t = 0.0;
        for (int i = 0; i < 8; i++) t += sh[i];
        atomicAdd(acc, t);
    }
}

__global__ void finalize_k(const double* __restrict__ acc, float* __restrict__ out, int n) {
    double inv = 1.0 / (double)(TT * BB);
    float loss = (float)((acc[0] + acc[1] + acc[2]) * inv);
    for (int i = 0; i < n; i++) out[i] = loss;
}

// ---------------- host ----------------
static void* symaddr(const void* sym) {
    void* p = nullptr;
    cudaGetSymbolAddress(&p, sym);
    return p;
}

extern "C" void kernel_launch(void* const* d_in, const int* in_sizes, int n_in,
                              void* d_out, int out_size)
{
    const float* emb     = (const float*)d_in[0];
    const float* action  = (const float*)d_in[1];
    const float* reward  = (const float*)d_in[2];
    const float* eps     = (const float*)d_in[3];
    const float* gru_Wih = (const float*)d_in[4];
    const float* gru_bih = (const float*)d_in[5];
    const float* gru_Whh = (const float*)d_in[6];
    const float* gru_bhh = (const float*)d_in[7];
    const float* st_W0 = (const float*)d_in[8];  const float* st_b0 = (const float*)d_in[9];
    const float* st_W1 = (const float*)d_in[10]; const float* st_b1 = (const float*)d_in[11];
    const float* st_W2 = (const float*)d_in[12]; const float* st_b2 = (const float*)d_in[13];
    const float* ep_W0 = (const float*)d_in[14]; const float* ep_b0 = (const float*)d_in[15];
    const float* ep_W1 = (const float*)d_in[16]; const float* ep_b1 = (const float*)d_in[17];
    const float* ep_W2 = (const float*)d_in[18]; const float* ep_b2 = (const float*)d_in[19];
    const float* rp_W0 = (const float*)d_in[20]; const float* rp_b0 = (const float*)d_in[21];
    const float* rp_W1 = (const float*)d_in[22]; const float* rp_b1 = (const float*)d_in[23];
    const float* rp_W2 = (const float*)d_in[24]; const float* rp_b2 = (const float*)d_in[25];

    float* carryA = (float*)symaddr(g_carryA);
    float* carryB = (float*)symaddr(g_carryB);
    float* zeroc  = (float*)symaddr(g_zeroc);
    float* y1     = (float*)symaddr(g_y1);
    float* y2     = (float*)symaddr(g_y2);
    float* qmu    = (float*)symaddr(g_qmu);
    float* qstd   = (float*)symaddr(g_qstd);
    float* P      = (float*)symaddr(g_P);
    float* PE     = (float*)symaddr(g_PE);
    float* E      = (float*)symaddr(g_E);
    float* praw   = (float*)symaddr(g_praw);
    float* e0     = (float*)symaddr(g_e0);
    float* e0l1   = (float*)symaddr(g_e0l1);
    float* b2p    = (float*)symaddr(g_b2p);
    double* acc   = (double*)symaddr(g_acc);
    bf16* stbf   = (bf16*)symaddr(g_states_bf);
    bf16* embbf  = (bf16*)symaddr(g_emb_bf);
    bf16* Ebf    = (bf16*)symaddr(g_E_bf);
    bf16* pcatbf = (bf16*)symaddr(g_pcat_bf);
    bf16* big1bf = (bf16*)symaddr(g_big1_bf);
    bf16* big2bf = (bf16*)symaddr(g_big2_bf);
    bf16* e0bf   = (bf16*)symaddr(g_e0_bf);
    bf16* stW0b  = (bf16*)symaddr(g_stW0b);
    bf16* stW1b  = (bf16*)symaddr(g_stW1b);
    bf16* stW2b  = (bf16*)symaddr(g_stW2b);
    bf16* epW0b  = (bf16*)symaddr(g_epW0b);
    bf16* epW1b  = (bf16*)symaddr(g_epW1b);
    bf16* epW2b  = (bf16*)symaddr(g_epW2b);
    bf16* rpW0b  = (bf16*)symaddr(g_rpW0b);
    bf16* rpW1b  = (bf16*)symaddr(g_rpW1b);
    bf16* WGh  = (bf16*)symaddr(g_WGh);   bf16* WGl  = (bf16*)symaddr(g_WGl);
    bf16* W0hh = (bf16*)symaddr(g_W0hh);  bf16* W0hl = (bf16*)symaddr(g_W0hl);
    bf16* W1h  = (bf16*)symaddr(g_W1h);   bf16* W1l  = (bf16*)symaddr(g_W1l);
    bf16* W2h  = (bf16*)symaddr(g_W2h);   bf16* W2l  = (bf16*)symaddr(g_W2l);

    zero_acc_k<<<1, 32>>>(acc);

    // conversions + prep
    cvt_bf_k<<<2048, 256>>>(emb,   embbf, (long)TBD * EMBD);
    cvt_bf_k<<<512, 256>>>(st_W0, stW0b, 512L * 1536);
    cvt_bf_k<<<256, 256>>>(st_W1, stW1b, 512L * 512);
    cvt_bf_k<<<64,  256>>>(st_W2, stW2b, 128L * 512);
    cvt_bf_k<<<256, 256>>>(ep_W0, epW0b, 512L * 576);
    cvt_bf_k<<<256, 256>>>(ep_W1, epW1b, 512L * 512);
    cvt_bf_k<<<512, 256>>>(ep_W2, epW2b, 1024L * 512);
    cvt_bf_k<<<256, 256>>>(rp_W0, rpW0b, 512L * 576);
    cvt_bf_k<<<256, 256>>>(rp_W1, rpW1b, 512L * 512);
    prep_P<<<TBD, 256>>>(action, gru_Wih, gru_bih, gru_bhh, P);
    prep_WG<<<1024, 256>>>(gru_Wih, gru_Whh, WGh, WGl);
    prep_split<<<256, 256>>>(st_W0, 1536, 512, W0hh, W0hl, 512L * 512);
    prep_split<<<256, 256>>>(st_W1, 512, 512, W1h, W1l, 512L * 512);
    prep_W2p<<<64, 256>>>(st_W2, st_b2, W2h, W2l, b2p);
    e0_l1<<<1, 256>>>(ep_b0, ep_W1, ep_b1, e0l1);
    e0_head<<<4, 256>>>(e0l1, ep_W2, ep_b2, e0);
    cvt_bf_k<<<4, 256>>>(e0, e0bf, EMBD);

    // PE = emb_prev @ st_W0[:,512:1536]^T + st_b0   (tensor core, rowShift)
    mma_gemm<0, true, true, false><<<dim3(4, 128), 256>>>(
        embbf, EMBD, stW0b + 512, 1536, st_b0, PE, nullptr, FEATD, EMBD);

    // sequential recurrence: persistent, split-bf16 tensor-core stages
    recur_k<<<NBLK, 256>>>(WGh, WGl, P, gru_bhh, W0hh, W0hl, PE,
                           W1h, W1l, st_b1, W2h, W2l, b2p,
                           eps, qmu, qstd, stbf, carryA, carryB, zeroc, y1, y2);

    // shared ep-MLP: E = ep_mlp(states) = emb_mu; row-shifted = pre_emb
    mma_gemm<1, false, false, true><<<dim3(4, 128), 256>>>(
        stbf, STATED, epW0b, STATED, ep_b0, nullptr, big1bf, FEATD, STATED);
    mma_gemm<1, false, false, true><<<dim3(4, 128), 256>>>(
        big1bf, FEATD, epW1b, FEATD, ep_b1, nullptr, big2bf, FEATD, FEATD);
    mma_gemm<0, false, true, true><<<dim3(8, 128), 256>>>(
        big2bf, FEATD, epW2b, FEATD, ep_b2, E, Ebf, EMBD, FEATD);

    // prior path
    build_pcat<<<TBD, 256>>>(stbf, Ebf, e0bf, pcatbf);
    mma_gemm<1, false, false, true><<<dim3(4, 128), 256>>>(
        pcatbf, 1536, stW0b, 1536, st_b0, nullptr, big1bf, FEATD, 1536);
    mma_gemm<1, false, false, true><<<dim3(4, 128), 256>>>(
        big1bf, FEATD, stW1b, FEATD, st_b1, nullptr, big2bf, FEATD, FEATD);
    mma_gemm<0, false, true, false><<<dim3(1, 128), 256>>>(
        big2bf, FEATD, stW2b, FEATD, st_b2, praw, nullptr, 128, FEATD);
    kl_reduce_k<<<1024, 256>>>(praw, qmu, qstd, acc + 0);

    // emb loss
    emb_reduce_k<<<2048, 256>>>(emb, E, acc + 1);

    // reward loss
    mma_gemm<1, false, false, true><<<dim3(4, 128), 256>>>(
        stbf, STATED, rpW0b, STATED, rp_b0, nullptr, big1bf, FEATD, STATED);
    mma_gemm<1, false, false, true><<<dim3(4, 128), 256>>>(
        big1bf, FEATD, rpW1b, FEATD, rp_b1, nullptr, big2bf, FEATD, FEATD);
    reward_reduce_k<<<512, 256>>>(big2bf, rp_W2, rp_b2, reward, acc + 2);

    finalize_k<<<1, 1>>>(acc, (float*)d_out, out_size);
}